// round 15
// baseline (speedup 1.0000x reference)
#include <cuda_runtime.h>
#include <cuda_fp16.h>
#include <mma.h>
#include <math.h>
#include <float.h>

using namespace nvcuda;

#define HID 128
#define MAX_N 20000
#define MAX_NC 5000
#define MAX_NC_PAD 5120
#define MAX_E 340000
#define MAX_EC 90000
#define KNN_K 3
#define RSPLIT 15
#define NPART (RSPLIT * 2 * 8)
#define TOPP 8
#define KNN_BLOCKS 304
#define GEMM_BLOCKS 304
#define LDT 136
#define LDX 132
#define BTILE 64
#define SCHUNK 1024

__device__ float g_lin [MAX_N * HID];
__device__ float g_linc[MAX_NC * HID];
__device__ float g_hr1 [MAX_N * HID];
__device__ float g_hr  [MAX_N * HID];
__device__ float g_hc1 [MAX_NC * HID];
__device__ float g_hc  [MAX_NC * HID];
__device__ float g_es  [MAX_N];
__device__ float g_ed  [MAX_N];
__device__ float g_esc [MAX_NC];
__device__ float g_edc [MAX_NC];
__device__ int   g_degr[MAX_N];
__device__ int   g_degc[MAX_NC];
__device__ int   g_rowptr [MAX_N + 1];
__device__ int   g_rowptrc[MAX_NC + 1];
__device__ int   g_wp  [MAX_N];
__device__ int   g_wpc [MAX_NC];
__device__ int   g_bsum [64];
__device__ int   g_bsumc[64];
__device__ int   g_csr_src [MAX_E];
__device__ int   g_csr_srcc[MAX_EC];
__device__ float g_rnorm[MAX_N];
__device__ __half g_hch[MAX_NC_PAD * HID];
__device__ __half g_hrh[MAX_N * HID];
__device__ float g_pv [NPART * MAX_NC_PAD];
__device__ int   g_pi [NPART * MAX_NC_PAD];
__device__ int   g_cand[MAX_NC * TOPP];
__device__ float g_sc  [MAX_NC * TOPP];
__device__ int   g_nn [MAX_NC * KNN_K];
__device__ float g_pool[MAX_N * HID];
__device__ int   g_cnt [MAX_N];
__device__ int   g_work;

/* ---------------- helpers ---------------- */
__device__ __forceinline__ unsigned smem_u32(const void* p) {
    unsigned a;
    asm("{ .reg .u64 t; cvta.to.shared.u64 t, %1; cvt.u32.u64 %0, t; }" : "=r"(a) : "l"(p));
    return a;
}
__device__ __forceinline__ void cp_async16(unsigned dst, const void* src, int src_bytes) {
    asm volatile("cp.async.cg.shared.global [%0], [%1], 16, %2;"
                 :: "r"(dst), "l"(src), "r"(src_bytes) : "memory");
}
#define CP_COMMIT() asm volatile("cp.async.commit_group;" ::: "memory")
#define CP_WAIT0()  asm volatile("cp.async.wait_group 0;" ::: "memory")

/* ---------------- bulk zero ---------------- */
__global__ void zero_kernel(int* degr, int nr, int* degc, int nc,
                            float* pool, long np, int* cnt, int* work) {
    long total = (long)nr + nc + np + nr + 1;
    for (long i = (long)blockIdx.x * blockDim.x + threadIdx.x; i < total;
         i += (long)gridDim.x * blockDim.x) {
        if (i < nr) degr[i] = 0;
        else if (i < (long)nr + nc) degc[i - nr] = 0;
        else if (i < (long)nr + nc + np) pool[i - nr - nc] = 0.f;
        else if (i < (long)nr + nc + np + nr) cnt[i - nr - nc - np] = 0;
        else *work = 0;
    }
}

/* ---------------- fused CSR build (both graphs) ---------------- */
__global__ void deg_both(const int* __restrict__ eir, int Er, int nr, int* degr,
                         const int* __restrict__ eic, int Ec, int nc, int* degc) {
    int i = blockIdx.x * blockDim.x + threadIdx.x;
    int totr = Er + nr;
    if (i < totr) {
        int dst = (i < Er) ? eir[Er + i] : (i - Er);
        atomicAdd(&degr[dst], 1);
    } else {
        int j = i - totr;
        if (j >= Ec + nc) return;
        int dst = (j < Ec) ? eic[Ec + j] : (j - Ec);
        atomicAdd(&degc[dst], 1);
    }
}

__device__ __forceinline__ int blockscan4(const int* __restrict__ deg, int base, int n,
                                          int v[4], int* warpsums) {
    int tid = threadIdx.x, lane = tid & 31, w = tid >> 5;
    int s = 0;
#pragma unroll
    for (int q = 0; q < 4; q++) {
        int i = base + tid * 4 + q;
        v[q] = (i < n) ? deg[i] : 0;
        s += v[q];
    }
    int x = s;
    for (int o = 1; o < 32; o <<= 1) {
        int y = __shfl_up_sync(0xffffffffu, x, o);
        if (lane >= o) x += y;
    }
    if (lane == 31) warpsums[w] = x;
    __syncthreads();
    if (w == 0) {
        int t = warpsums[lane & 7];
        for (int o = 1; o < 8; o <<= 1) {
            int y = __shfl_up_sync(0xffffffffu, t, o);
            if ((lane & 7) >= o) t += y;
        }
        if (lane < 8) warpsums[lane] = t;
    }
    __syncthreads();
    return (w > 0 ? warpsums[w - 1] : 0) + x - s;
}

__global__ void scan_p1_both(const int* __restrict__ degr, int nr, int ncr, int* bsumr,
                             const int* __restrict__ degc, int nc, int* bsumc) {
    __shared__ int warpsums[32];
    int v[4];
    if ((int)blockIdx.x < ncr) {
        int excl = blockscan4(degr, blockIdx.x * SCHUNK, nr, v, warpsums);
        if (threadIdx.x == 255) bsumr[blockIdx.x] = excl + v[0] + v[1] + v[2] + v[3];
    } else {
        int b = blockIdx.x - ncr;
        int excl = blockscan4(degc, b * SCHUNK, nc, v, warpsums);
        if (threadIdx.x == 255) bsumc[b] = excl + v[0] + v[1] + v[2] + v[3];
    }
}

__device__ __forceinline__ void warp_exscan(int* bsum, int nb, int n, int* rowptr) {
    int lane = threadIdx.x & 31;
    int acc = 0;
    for (int b = 0; b < nb; b += 32) {
        int v = (b + lane < nb) ? bsum[b + lane] : 0;
        int x = v;
        for (int o = 1; o < 32; o <<= 1) {
            int y = __shfl_up_sync(0xffffffffu, x, o);
            if (lane >= o) x += y;
        }
        if (b + lane < nb) bsum[b + lane] = acc + x - v;
        int tot = __shfl_sync(0xffffffffu, x, 31);
        acc += tot;
    }
    if (lane == 0) rowptr[n] = acc;
}

__global__ void scan_p2_both(int* bsumr, int nbr, int nr, int* rowptrr,
                             int* bsumc, int nbc, int nc, int* rowptrc) {
    if (blockIdx.x == 0) warp_exscan(bsumr, nbr, nr, rowptrr);
    else                 warp_exscan(bsumc, nbc, nc, rowptrc);
}

__global__ void scan_p3_both(const int* __restrict__ degr, int nr, int ncr,
                             const int* __restrict__ bsumr, int* rowptrr, int* wpr,
                             const int* __restrict__ degc, int nc,
                             const int* __restrict__ bsumc, int* rowptrc, int* wpc) {
    __shared__ int warpsums[32];
    int v[4];
    const int* deg; const int* bsum; int* rowptr; int* wp; int n, b;
    if ((int)blockIdx.x < ncr) { deg = degr; bsum = bsumr; rowptr = rowptrr; wp = wpr; n = nr; b = blockIdx.x; }
    else { deg = degc; bsum = bsumc; rowptr = rowptrc; wp = wpc; n = nc; b = blockIdx.x - ncr; }
    int base = b * SCHUNK;
    int excl = blockscan4(deg, base, n, v, warpsums) + bsum[b];
#pragma unroll
    for (int q = 0; q < 4; q++) {
        int i = base + threadIdx.x * 4 + q;
        if (i < n) { rowptr[i] = excl; wp[i] = excl; }
        excl += v[q];
    }
}

__global__ void scatter_both(const int* __restrict__ eir, int Er, int nr, int* wpr, int* srcr,
                             const int* __restrict__ eic, int Ec, int nc, int* wpc, int* srcc) {
    int i = blockIdx.x * blockDim.x + threadIdx.x;
    int totr = Er + nr;
    if (i < totr) {
        int src = (i < Er) ? eir[i] : (i - Er);
        int dst = (i < Er) ? eir[Er + i] : (i - Er);
        int pos = atomicAdd(&wpr[dst], 1);
        srcr[pos] = src;
    } else {
        int j = i - totr;
        if (j >= Ec + nc) return;
        int src = (j < Ec) ? eic[j] : (j - Ec);
        int dst = (j < Ec) ? eic[Ec + j] : (j - Ec);
        int pos = atomicAdd(&wpc[dst], 1);
        srcc[pos] = src;
    }
}

/* ---------------- layer-1 linear (d_in=6) + dots, both ---------------- */
__device__ __forceinline__ void lin1_body(const float* __restrict__ x, const float* __restrict__ W,
                                          const float* __restrict__ a_s, const float* __restrict__ a_d,
                                          float* __restrict__ h, float* __restrict__ es,
                                          float* __restrict__ ed, int node, int d_in) {
    int f = threadIdx.x;
    __shared__ float xs[HID], r1[HID], r2[HID];
    if (f < d_in) xs[f] = x[node * d_in + f];
    __syncthreads();
    float acc = 0.f;
    for (int k = 0; k < d_in; k++) acc += xs[k] * W[k * HID + f];
    h[node * HID + f] = acc;
    r1[f] = acc * a_s[f];
    r2[f] = acc * a_d[f];
    __syncthreads();
    for (int s = 64; s > 0; s >>= 1) {
        if (f < s) { r1[f] += r1[f + s]; r2[f] += r2[f + s]; }
        __syncthreads();
    }
    if (f == 0) { es[node] = r1[0]; ed[node] = r2[0]; }
}

__global__ void lin1_both(const float* xr, const float* Wr, const float* asr, const float* adr,
                          float* hr, float* esr, float* edr, int nr,
                          const float* xc, const float* Wc, const float* asc, const float* adc,
                          float* hc, float* esc, float* edc, int nc) {
    if ((int)blockIdx.x < nr)
        lin1_body(xr, Wr, asr, adr, hr, esr, edr, blockIdx.x, 6);
    else
        lin1_body(xc, Wc, asc, adc, hc, esc, edc, blockIdx.x - nr, 6);
}

/* ------- layer-2 persistent GEMM + fused dots, both (2 CTAs/SM target) ------- */
__global__ void __launch_bounds__(256, 2)
gemm128_both(const float* __restrict__ xr, const float* __restrict__ Wr,
             const float* __restrict__ asr, const float* __restrict__ adr,
             float* __restrict__ hor, float* __restrict__ esr, float* __restrict__ edr,
             int nr, int splitB,
             const float* __restrict__ xc, const float* __restrict__ Wc,
             const float* __restrict__ asc, const float* __restrict__ adc,
             float* __restrict__ hoc, float* __restrict__ esc, float* __restrict__ edc,
             int nc) {
    extern __shared__ float sm[];
    float* Ws = sm;
    float* xs = sm + 128 * 128;
    int t = threadIdx.x, tx = t & 15, ty = t >> 4;

    const float *x, *W, *a_s, *a_d;
    float *h, *es, *ed;
    int n, b0, gs;
    if ((int)blockIdx.x < splitB) {
        x = xr; W = Wr; a_s = asr; a_d = adr; h = hor; es = esr; ed = edr;
        n = nr; b0 = blockIdx.x; gs = splitB;
    } else {
        x = xc; W = Wc; a_s = asc; a_d = adc; h = hoc; es = esc; ed = edc;
        n = nc; b0 = blockIdx.x - splitB; gs = gridDim.x - splitB;
    }

    for (int i = t * 4; i < 128 * 128; i += 1024)
        *(float4*)&Ws[i] = *(const float4*)&W[i];

    float sv[8], dv[8];
#pragma unroll
    for (int j = 0; j < 8; j++) { sv[j] = a_s[tx * 8 + j]; dv[j] = a_d[tx * 8 + j]; }

    for (int nb = b0 * 64; nb < n; nb += gs * 64) {
        __syncthreads();
#pragma unroll
        for (int m = 0; m < 8; m++) {
            int idx = t + m * 256;
            int row = idx >> 5, c4 = idx & 31;
            float4 v = make_float4(0.f, 0.f, 0.f, 0.f);
            if (nb + row < n) v = ((const float4*)x)[(size_t)(nb + row) * 32 + c4];
            *(float4*)&xs[row * LDX + c4 * 4] = v;
        }
        __syncthreads();
        float acc[4][8];
#pragma unroll
        for (int i = 0; i < 4; i++)
#pragma unroll
            for (int j = 0; j < 8; j++) acc[i][j] = 0.f;
#pragma unroll 4
        for (int k = 0; k < 128; k++) {
            float a0 = xs[(ty * 4 + 0) * LDX + k];
            float a1 = xs[(ty * 4 + 1) * LDX + k];
            float a2 = xs[(ty * 4 + 2) * LDX + k];
            float a3 = xs[(ty * 4 + 3) * LDX + k];
            float4 b0v = *(const float4*)&Ws[k * 128 + tx * 8];
            float4 b1v = *(const float4*)&Ws[k * 128 + tx * 8 + 4];
            float bb[8] = {b0v.x, b0v.y, b0v.z, b0v.w, b1v.x, b1v.y, b1v.z, b1v.w};
#pragma unroll
            for (int j = 0; j < 8; j++) {
                acc[0][j] += a0 * bb[j];
                acc[1][j] += a1 * bb[j];
                acc[2][j] += a2 * bb[j];
                acc[3][j] += a3 * bb[j];
            }
        }
#pragma unroll
        for (int i = 0; i < 4; i++) {
            int node = nb + ty * 4 + i;
            if (node < n) {
                *(float4*)&h[(size_t)node * 128 + tx * 8]     = make_float4(acc[i][0], acc[i][1], acc[i][2], acc[i][3]);
                *(float4*)&h[(size_t)node * 128 + tx * 8 + 4] = make_float4(acc[i][4], acc[i][5], acc[i][6], acc[i][7]);
            }
            float ps = 0.f, pd = 0.f;
#pragma unroll
            for (int j = 0; j < 8; j++) { ps += acc[i][j] * sv[j]; pd += acc[i][j] * dv[j]; }
            for (int o = 8; o > 0; o >>= 1) {
                ps += __shfl_down_sync(0xffffffffu, ps, o, 16);
                pd += __shfl_down_sync(0xffffffffu, pd, o, 16);
            }
            if (tx == 0 && node < n) { es[node] = ps; ed[node] = pd; }
        }
    }
}

/* --------- softmax + aggregate, both --------- */
__device__ __forceinline__ void agg_body(const float* __restrict__ h, const float* __restrict__ bias,
                                         const int* __restrict__ rowptr, const int* __restrict__ csr_src,
                                         const float* __restrict__ es, const float* __restrict__ ed,
                                         float* __restrict__ out, __half* __restrict__ outh,
                                         float* __restrict__ rn, int node, int lane) {
    int b0 = rowptr[node], b1 = rowptr[node + 1];
    float edn = ed[node];

    float m = -FLT_MAX;
    for (int j = b0 + lane; j < b1; j += 32) {
        float e = es[csr_src[j]] + edn;
        e = (e > 0.f) ? e : 0.2f * e;
        m = fmaxf(m, e);
    }
    for (int o = 16; o > 0; o >>= 1) m = fmaxf(m, __shfl_down_sync(0xffffffffu, m, o));
    m = __shfl_sync(0xffffffffu, m, 0);

    float s = 0.f;
    for (int j = b0 + lane; j < b1; j += 32) {
        float e = es[csr_src[j]] + edn;
        e = (e > 0.f) ? e : 0.2f * e;
        s += __expf(e - m);
    }
    for (int o = 16; o > 0; o >>= 1) s += __shfl_down_sync(0xffffffffu, s, o);
    s = __shfl_sync(0xffffffffu, s, 0);
    float inv = 1.f / fmaxf(s, 1e-16f);

    const float4* h4 = (const float4*)h;
    float4 acc = make_float4(0.f, 0.f, 0.f, 0.f);
    for (int j = b0; j < b1; j++) {
        int src = csr_src[j];
        float e = es[src] + edn;
        e = (e > 0.f) ? e : 0.2f * e;
        float w = __expf(e - m) * inv;
        float4 hv = h4[src * 32 + lane];
        acc.x += w * hv.x; acc.y += w * hv.y; acc.z += w * hv.z; acc.w += w * hv.w;
    }
    float4 bb = ((const float4*)bias)[lane];
    acc.x = fmaxf(acc.x + bb.x, 0.f); acc.y = fmaxf(acc.y + bb.y, 0.f);
    acc.z = fmaxf(acc.z + bb.z, 0.f); acc.w = fmaxf(acc.w + bb.w, 0.f);
    ((float4*)out)[node * 32 + lane] = acc;

    if (outh) {
        __half2 p0 = __halves2half2(__float2half_rn(acc.x), __float2half_rn(acc.y));
        __half2 p1 = __halves2half2(__float2half_rn(acc.z), __float2half_rn(acc.w));
        ((__half2*)outh)[node * 64 + lane * 2]     = p0;
        ((__half2*)outh)[node * 64 + lane * 2 + 1] = p1;
    }
    if (rn) {
        float q = acc.x * acc.x + acc.y * acc.y + acc.z * acc.z + acc.w * acc.w;
        for (int o = 16; o > 0; o >>= 1) q += __shfl_down_sync(0xffffffffu, q, o);
        if (lane == 0) rn[node] = q;
    }
}

__global__ void agg_both(const float* hrI, const float* br, const int* rpr, const int* srcr,
                         const float* esr, const float* edr, float* outr, __half* outhr,
                         float* rnr, int nr,
                         const float* hcI, const float* bc, const int* rpc, const int* srcc,
                         const float* esc, const float* edc, float* outc, __half* outhc,
                         float* rnc, int nc) {
    int wrp = (blockIdx.x * blockDim.x + threadIdx.x) >> 5;
    int lane = threadIdx.x & 31;
    if (wrp < nr)
        agg_body(hrI, br, rpr, srcr, esr, edr, outr, outhr, rnr, wrp, lane);
    else if (wrp < nr + nc)
        agg_body(hcI, bc, rpc, srcc, esc, edc, outc, outhc, rnc, wrp - nr, lane);
}

/* ---------------- KNN selection helpers ---------------- */
__device__ __forceinline__ bool bet(float v, int id, float v2, int id2) {
    return v < v2 || (v == v2 && id < id2);
}
__device__ __forceinline__ void top3_insert(float v, int id, float tv[3], int ti[3]) {
    if (!bet(v, id, tv[2], ti[2])) return;
    tv[2] = v; ti[2] = id;
    if (bet(tv[2], ti[2], tv[1], ti[1])) {
        float f = tv[1]; tv[1] = tv[2]; tv[2] = f;
        int q = ti[1]; ti[1] = ti[2]; ti[2] = q;
    }
    if (bet(tv[1], ti[1], tv[0], ti[0])) {
        float f = tv[0]; tv[0] = tv[1]; tv[1] = f;
        int q = ti[0]; ti[0] = ti[1]; ti[1] = q;
    }
}
#define T8SW(a, b) \
    if (bet(tv[b], ti[b], tv[a], ti[a])) { \
        float f_ = tv[a]; tv[a] = tv[b]; tv[b] = f_; \
        int q_ = ti[a]; ti[a] = ti[b]; ti[b] = q_; }
__device__ __forceinline__ void top8_insert(float s, int id, float tv[8], int ti[8]) {
    if (!bet(s, id, tv[7], ti[7])) return;
    tv[7] = s; ti[7] = id;
    T8SW(6, 7) T8SW(5, 6) T8SW(4, 5) T8SW(3, 4) T8SW(2, 3) T8SW(1, 2) T8SW(0, 1)
}

/* Persistent wmma KNN: A fragments cached in registers per c-tile. */
__global__ void __launch_bounds__(256, 2)
knn_wmma_kernel(const __half* __restrict__ hch, const __half* __restrict__ hrh,
                const float* __restrict__ rn,
                int n_c, int n_r, int n_rtiles, int tiles_per, int n_items,
                float* __restrict__ pv, int* __restrict__ pi) {
    extern __shared__ char dsm[];
    __half* As  = (__half*)dsm;
    __half* Bs  = As + 128 * LDT;
    float*  scr = (float*)(Bs + 2 * BTILE * LDT);
    __shared__ int s_item;

    int tid = threadIdx.x, wid = tid >> 5, lane = tid & 31;
    int crow = lane & 15, chalf = lane >> 4;
    float* myscr = scr + wid * 256;
    unsigned bbase = smem_u32(Bs);

    int row0 = tid >> 4, k80 = tid & 15;
    int prev_ct = -1;
    wmma::fragment<wmma::matrix_a, 16, 16, 16, __half, wmma::row_major> af[8];

    for (;;) {
        __syncthreads();
        if (tid == 0) s_item = atomicAdd(&g_work, 1);
        __syncthreads();
        int item = s_item;
        if (item >= n_items) break;
        int ct = item / RSPLIT;
        int rs = item - ct * RSPLIT;
        int cbase = ct * 128;
        int t0 = rs * tiles_per;
        int t1 = min(t0 + tiles_per, n_rtiles);
        int my_c = cbase + wid * 16 + crow;

        float tv[8]; int ti[8];
#pragma unroll
        for (int s = 0; s < 8; s++) { tv[s] = FLT_MAX; ti[s] = 0x7fffffff; }

        if (t0 < t1) {
            if (ct != prev_ct) {
#pragma unroll
                for (int m = 0; m < 8; m++) {
                    int idx = tid + m * 256;
                    int row = idx >> 4, k8 = idx & 15;
                    int c = cbase + row;
                    uint4 v = make_uint4(0, 0, 0, 0);
                    if (c < n_c) v = ((const uint4*)hch)[c * 16 + k8];
                    *(uint4*)&As[row * LDT + k8 * 8] = v;
                }
                __syncthreads();
#pragma unroll
                for (int k = 0; k < 8; k++)
                    wmma::load_matrix_sync(af[k], &As[(wid * 16) * LDT + k * 16], LDT);
                prev_ct = ct;
            }

            {
                int rbase = t0 * BTILE;
#pragma unroll
                for (int m = 0; m < 4; m++) {
                    int row = row0 + m * 16;
                    int r = rbase + row;
                    int ok = (r < n_r);
                    const void* src = hrh + (size_t)(ok ? r : 0) * 128 + k80 * 8;
                    cp_async16(bbase + (row * LDT + k80 * 8) * 2, src, ok ? 16 : 0);
                }
                CP_COMMIT();
            }

            for (int tt = t0; tt < t1; tt++) {
                int cur = (tt - t0) & 1;
                CP_WAIT0();
                __syncthreads();
                if (tt + 1 < t1) {
                    int nxt = cur ^ 1;
                    int rbase2 = (tt + 1) * BTILE;
#pragma unroll
                    for (int m = 0; m < 4; m++) {
                        int row = row0 + m * 16;
                        int r = rbase2 + row;
                        int ok = (r < n_r);
                        const void* src = hrh + (size_t)(ok ? r : 0) * 128 + k80 * 8;
                        cp_async16(bbase + (nxt * BTILE * LDT + row * LDT + k80 * 8) * 2, src, ok ? 16 : 0);
                    }
                    CP_COMMIT();
                }

                const __half* Bc = Bs + cur * BTILE * LDT;
                int rbase = tt * BTILE;

                wmma::fragment<wmma::accumulator, 16, 16, 16, float> acc[4];
#pragma unroll
                for (int f = 0; f < 4; f++) wmma::fill_fragment(acc[f], 0.f);
#pragma unroll
                for (int k = 0; k < 8; k++) {
#pragma unroll
                    for (int f = 0; f < 4; f++) {
                        wmma::fragment<wmma::matrix_b, 16, 16, 16, __half, wmma::col_major> bf;
                        wmma::load_matrix_sync(bf, &Bc[(f * 16) * LDT + k * 16], LDT);
                        wmma::mma_sync(acc[f], af[k], bf, acc[f]);
                    }
                }

#pragma unroll
                for (int f = 0; f < 4; f++) {
                    wmma::store_matrix_sync(myscr, acc[f], 16, wmma::mem_row_major);
                    __syncwarp();
                    int cb = f * 16 + chalf * 8;
#pragma unroll
                    for (int j = 0; j < 8; j++) {
                        int r = rbase + cb + j;
                        float rv = (r < n_r) ? rn[r] : 1e30f;
                        float d = myscr[crow * 16 + chalf * 8 + j];
                        top8_insert(fmaf(-2.f, d, rv), r, tv, ti);
                    }
                    __syncwarp();
                }
            }
        }

        if (my_c < n_c) {
            int ebase = (rs * 2 + chalf) * 8;
#pragma unroll
            for (int s = 0; s < 8; s++) {
                pv[(ebase + s) * MAX_NC_PAD + my_c] = tv[s];
                pi[(ebase + s) * MAX_NC_PAD + my_c] = ti[s];
            }
        }
    }
}

__global__ void merge8_kernel(const float* __restrict__ pv, const int* __restrict__ pi,
                              int n_c, int n_r, int* __restrict__ cand) {
    int c = blockIdx.x * blockDim.x + threadIdx.x;
    if (c >= n_c) return;
    float tv[8]; int ti[8];
#pragma unroll
    for (int s = 0; s < 8; s++) { tv[s] = FLT_MAX; ti[s] = 0x7fffffff; }
    for (int e = 0; e < NPART; e++) {
        int id = pi[e * MAX_NC_PAD + c];
        if ((unsigned)id < (unsigned)n_r)
            top8_insert(pv[e * MAX_NC_PAD + c], id, tv, ti);
    }
#pragma unroll
    for (int j = 0; j < 8; j++) cand[c * TOPP + j] = ti[j];
}

__global__ void rescore_kernel(const int* __restrict__ cand, const float* __restrict__ hc,
                               const float* __restrict__ hr, const float* __restrict__ rn,
                               int n_c, int n_r, float* __restrict__ sc) {
    int gw = (blockIdx.x * blockDim.x + threadIdx.x) >> 5;
    int lane = threadIdx.x & 31;
    if (gw >= n_c * TOPP) return;
    int c = gw / TOPP, j = gw - c * TOPP;
    int id = cand[c * TOPP + j];
    float s = FLT_MAX;
    if ((unsigned)id < (unsigned)n_r) {
        float4 a = ((const float4*)hc)[c * 32 + lane];
        float4 b = ((const float4*)hr)[id * 32 + lane];
        float d = a.x * b.x + a.y * b.y + a.z * b.z + a.w * b.w;
        for (int o = 16; o > 0; o >>= 1) d += __shfl_down_sync(0xffffffffu, d, o);
        s = rn[id] - 2.f * d;
    }
    if (lane == 0) sc[c * TOPP + j] = s;
}

__global__ void final3_kernel(const float* __restrict__ sc, const int* __restrict__ cand,
                              int n_c, int n_r, int* __restrict__ nn) {
    int c = blockIdx.x * blockDim.x + threadIdx.x;
    if (c >= n_c) return;
    float bv[3] = {FLT_MAX, FLT_MAX, FLT_MAX};
    int   bi[3] = {0x7fffffff, 0x7fffffff, 0x7fffffff};
#pragma unroll
    for (int j = 0; j < TOPP; j++) {
        int id = cand[c * TOPP + j];
        if ((unsigned)id < (unsigned)n_r)
            top3_insert(sc[c * TOPP + j], id, bv, bi);
    }
    nn[c * 3 + 0] = bi[0]; nn[c * 3 + 1] = bi[1]; nn[c * 3 + 2] = bi[2];
}

/* ---------------- pooling + decode ---------------- */
__global__ void assign_kernel(const float* __restrict__ hc, const int* __restrict__ nn,
                              float* __restrict__ pool, int* __restrict__ cnt, int n_c) {
    int g = blockIdx.x * blockDim.x + threadIdx.x;
    int w = g >> 5, lane = g & 31;
    if (w >= n_c * KNN_K) return;
    int c = w / KNN_K;
    int idx = nn[w];
    if (lane == 0) atomicAdd(&cnt[idx], 1);
    float4 hv = ((const float4*)hc)[c * 32 + lane];
    atomicAdd(&pool[idx * HID + lane * 4 + 0], hv.x);
    atomicAdd(&pool[idx * HID + lane * 4 + 1], hv.y);
    atomicAdd(&pool[idx * HID + lane * 4 + 2], hv.z);
    atomicAdd(&pool[idx * HID + lane * 4 + 3], hv.w);
}

__global__ void decode_kernel(const float* __restrict__ hr, const float* __restrict__ pool,
                              const int* __restrict__ cnt, const float* __restrict__ Wd,
                              const float* __restrict__ bd, float* __restrict__ out, int n) {
    int i = (blockIdx.x * blockDim.x + threadIdx.x) >> 5;
    int lane = threadIdx.x & 31;
    if (i >= n) return;
    float inv = 1.f / fmaxf((float)cnt[i], 1.f);
    float a0 = 0.f, a1 = 0.f, a2 = 0.f;
    for (int f = lane; f < HID; f += 32) {
        float v = hr[i * HID + f];
        a0 += v * Wd[f * 3 + 0]; a1 += v * Wd[f * 3 + 1]; a2 += v * Wd[f * 3 + 2];
        float p = pool[i * HID + f] * inv;
        a0 += p * Wd[(HID + f) * 3 + 0]; a1 += p * Wd[(HID + f) * 3 + 1]; a2 += p * Wd[(HID + f) * 3 + 2];
    }
    for (int o = 16; o > 0; o >>= 1) {
        a0 += __shfl_down_sync(0xffffffffu, a0, o);
        a1 += __shfl_down_sync(0xffffffffu, a1, o);
        a2 += __shfl_down_sync(0xffffffffu, a2, o);
    }
    if (lane == 0) {
        out[i * 3 + 0] = a0 + bd[0];
        out[i * 3 + 1] = a1 + bd[1];
        out[i * 3 + 2] = a2 + bd[2];
    }
}

/* ---------------- host ---------------- */
extern "C" void kernel_launch(void* const* d_in, const int* in_sizes, int n_in,
                              void* d_out, int out_size) {
    const float* x_r  = (const float*)d_in[0];
    const float* x_c  = (const float*)d_in[1];
    const int*   ei_r = (const int*)d_in[2];
    const int*   ei_c = (const int*)d_in[3];
    const float* W_r1 = (const float*)d_in[5];
    const float* as_r1 = (const float*)d_in[6];
    const float* ad_r1 = (const float*)d_in[7];
    const float* b_r1  = (const float*)d_in[8];
    const float* W_r2 = (const float*)d_in[9];
    const float* as_r2 = (const float*)d_in[10];
    const float* ad_r2 = (const float*)d_in[11];
    const float* b_r2  = (const float*)d_in[12];
    const float* W_c1 = (const float*)d_in[13];
    const float* as_c1 = (const float*)d_in[14];
    const float* ad_c1 = (const float*)d_in[15];
    const float* b_c1  = (const float*)d_in[16];
    const float* W_c2 = (const float*)d_in[17];
    const float* as_c2 = (const float*)d_in[18];
    const float* ad_c2 = (const float*)d_in[19];
    const float* b_c2  = (const float*)d_in[20];
    const float* W_dec = (const float*)d_in[21];
    const float* b_dec = (const float*)d_in[22];
    float* out = (float*)d_out;

    int n_r = in_sizes[0] / 6;
    int n_c = in_sizes[1] / 6;
    int E_r = in_sizes[2] / 2;
    int E_c = in_sizes[3] / 2;

    float *lin, *linc, *hr1, *hr, *hc1, *hc, *es, *ed, *esc, *edc, *rnorm, *pv, *pool, *sc;
    __half *hch, *hrh;
    int *degr, *degc, *rowptr, *rowptrc, *wp, *wpc, *bsum, *bsumc;
    int *csr_src, *csr_srcc, *pi, *nn, *cnt, *work, *cand;
    cudaGetSymbolAddress((void**)&lin, g_lin);
    cudaGetSymbolAddress((void**)&linc, g_linc);
    cudaGetSymbolAddress((void**)&hr1, g_hr1);
    cudaGetSymbolAddress((void**)&hr,  g_hr);
    cudaGetSymbolAddress((void**)&hc1, g_hc1);
    cudaGetSymbolAddress((void**)&hc,  g_hc);
    cudaGetSymbolAddress((void**)&es,  g_es);
    cudaGetSymbolAddress((void**)&ed,  g_ed);
    cudaGetSymbolAddress((void**)&esc, g_esc);
    cudaGetSymbolAddress((void**)&edc, g_edc);
    cudaGetSymbolAddress((void**)&degr, g_degr);
    cudaGetSymbolAddress((void**)&degc, g_degc);
    cudaGetSymbolAddress((void**)&rowptr, g_rowptr);
    cudaGetSymbolAddress((void**)&rowptrc, g_rowptrc);
    cudaGetSymbolAddress((void**)&wp,  g_wp);
    cudaGetSymbolAddress((void**)&wpc, g_wpc);
    cudaGetSymbolAddress((void**)&bsum, g_bsum);
    cudaGetSymbolAddress((void**)&bsumc, g_bsumc);
    cudaGetSymbolAddress((void**)&csr_src, g_csr_src);
    cudaGetSymbolAddress((void**)&csr_srcc, g_csr_srcc);
    cudaGetSymbolAddress((void**)&rnorm, g_rnorm);
    cudaGetSymbolAddress((void**)&hch, g_hch);
    cudaGetSymbolAddress((void**)&hrh, g_hrh);
    cudaGetSymbolAddress((void**)&pv, g_pv);
    cudaGetSymbolAddress((void**)&pi, g_pi);
    cudaGetSymbolAddress((void**)&cand, g_cand);
    cudaGetSymbolAddress((void**)&sc, g_sc);
    cudaGetSymbolAddress((void**)&nn, g_nn);
    cudaGetSymbolAddress((void**)&pool, g_pool);
    cudaGetSymbolAddress((void**)&cnt, g_cnt);
    cudaGetSymbolAddress((void**)&work, g_work);

    size_t gemm_smem = (size_t)(128 * 128 + 64 * LDX) * sizeof(float);
    cudaFuncSetAttribute(gemm128_both, cudaFuncAttributeMaxDynamicSharedMemorySize,
                         (int)gemm_smem);

    {
        long np = (long)n_r * HID;
        long total = (long)n_r + n_c + np + n_r + 1;
        int zb = (int)((total + 255) / 256);
        if (zb > 4096) zb = 4096;
        zero_kernel<<<zb, 256>>>(degr, n_r, degc, n_c, pool, np, cnt, work);
    }

    int totr = E_r + n_r, totc = E_c + n_c;
    int ncr = (n_r + SCHUNK - 1) / SCHUNK;
    int ncc = (n_c + SCHUNK - 1) / SCHUNK;

    deg_both<<<(totr + totc + 255) / 256, 256>>>(ei_r, E_r, n_r, degr, ei_c, E_c, n_c, degc);
    scan_p1_both<<<ncr + ncc, 256>>>(degr, n_r, ncr, bsum, degc, n_c, bsumc);
    scan_p2_both<<<2, 32>>>(bsum, ncr, n_r, rowptr, bsumc, ncc, n_c, rowptrc);
    scan_p3_both<<<ncr + ncc, 256>>>(degr, n_r, ncr, bsum, rowptr, wp,
                                     degc, n_c, bsumc, rowptrc, wpc);
    scatter_both<<<(totr + totc + 255) / 256, 256>>>(ei_r, E_r, n_r, wp, csr_src,
                                                     ei_c, E_c, n_c, wpc, csr_srcc);

    lin1_both<<<n_r + n_c, 128>>>(x_r, W_r1, as_r1, ad_r1, hr1, es, ed, n_r,
                                  x_c, W_c1, as_c1, ad_c1, hc1, esc, edc, n_c);
    agg_both<<<(n_r + n_c + 7) / 8, 256>>>(hr1, b_r1, rowptr, csr_src, es, ed,
                                           lin, (__half*)0, (float*)0, n_r,
                                           hc1, b_c1, rowptrc, csr_srcc, esc, edc,
                                           linc, (__half*)0, (float*)0, n_c);
    {
        int splitB = (int)((long)GEMM_BLOCKS * n_r / (n_r + n_c));
        if (splitB < 1) splitB = 1;
        if (splitB > GEMM_BLOCKS - 1) splitB = GEMM_BLOCKS - 1;
        gemm128_both<<<GEMM_BLOCKS, 256, gemm_smem>>>(lin, W_r2, as_r2, ad_r2, hr1, es, ed, n_r, splitB,
                                                      linc, W_c2, as_c2, ad_c2, hc1, esc, edc, n_c);
    }
    agg_both<<<(n_r + n_c + 7) / 8, 256>>>(hr1, b_r2, rowptr, csr_src, es, ed,
                                           hr, hrh, rnorm, n_r,
                                           hc1, b_c2, rowptrc, csr_srcc, esc, edc,
                                           hc, hch, (float*)0, n_c);

    /* KNN */
    int n_rtiles = (n_r + BTILE - 1) / BTILE;
    int tiles_per = (n_rtiles + RSPLIT - 1) / RSPLIT;
    int nct = (n_c + 127) / 128;
    int n_items = nct * RSPLIT;
    size_t knn_smem = (size_t)((128 + 2 * BTILE) * LDT) * sizeof(__half)
                    + (size_t)(8 * 256) * sizeof(float);
    cudaFuncSetAttribute(knn_wmma_kernel, cudaFuncAttributeMaxDynamicSharedMemorySize,
                         (int)knn_smem);
    knn_wmma_kernel<<<KNN_BLOCKS, 256, knn_smem>>>(hch, hrh, rnorm, n_c, n_r,
                                                   n_rtiles, tiles_per, n_items, pv, pi);
    merge8_kernel<<<(n_c + 127) / 128, 128>>>(pv, pi, n_c, n_r, cand);
    rescore_kernel<<<(n_c * TOPP * 32 + 255) / 256, 256>>>(cand, hc, hr, rnorm, n_c, n_r, sc);
    final3_kernel<<<(n_c + 255) / 256, 256>>>(sc, cand, n_c, n_r, nn);

    assign_kernel<<<(n_c * KNN_K * 32 + 255) / 256, 256>>>(hc, nn, pool, cnt, n_c);
    decode_kernel<<<(n_r * 32 + 255) / 256, 256>>>(hr, pool, cnt, W_dec, b_dec, out, n_r);
}

// round 16
// speedup vs baseline: 1.0326x; 1.0326x over previous
#include <cuda_runtime.h>
#include <cuda_fp16.h>
#include <mma.h>
#include <math.h>
#include <float.h>

using namespace nvcuda;

#define HID 128
#define MAX_N 20000
#define MAX_NC 5000
#define MAX_NC_PAD 5120
#define MAX_E 340000
#define MAX_EC 90000
#define KNN_K 3
#define RSPLIT 15
#define NPART (RSPLIT * 2 * 8)
#define TOPP 8
#define KNN_BLOCKS 304
#define LDT 136
#define LDX 132
#define BTILE 64
#define SCHUNK 1024

__device__ float g_lin [MAX_N * HID];
__device__ float g_linc[MAX_NC * HID];
__device__ float g_hr1 [MAX_N * HID];
__device__ float g_hr  [MAX_N * HID];
__device__ float g_hc1 [MAX_NC * HID];
__device__ float g_hc  [MAX_NC * HID];
__device__ float g_es  [MAX_N];
__device__ float g_ed  [MAX_N];
__device__ float g_esc [MAX_NC];
__device__ float g_edc [MAX_NC];
__device__ int   g_degr[MAX_N];
__device__ int   g_degc[MAX_NC];
__device__ int   g_rowptr [MAX_N + 1];
__device__ int   g_rowptrc[MAX_NC + 1];
__device__ int   g_wp  [MAX_N];
__device__ int   g_wpc [MAX_NC];
__device__ int   g_bsum [64];
__device__ int   g_bsumc[64];
__device__ int   g_csr_src [MAX_E];
__device__ int   g_csr_srcc[MAX_EC];
__device__ float g_rnorm[MAX_N];
__device__ __half g_hch[MAX_NC_PAD * HID];
__device__ __half g_hrh[MAX_N * HID];
__device__ float g_pv [NPART * MAX_NC_PAD];
__device__ int   g_pi [NPART * MAX_NC_PAD];
__device__ int   g_cand[MAX_NC * TOPP];
__device__ float g_sc  [MAX_NC * TOPP];
__device__ int   g_nn [MAX_NC * KNN_K];
__device__ float g_pool[MAX_N * HID];
__device__ int   g_cnt [MAX_N];
__device__ int   g_work;

/* ---------------- helpers ---------------- */
__device__ __forceinline__ unsigned smem_u32(const void* p) {
    unsigned a;
    asm("{ .reg .u64 t; cvta.to.shared.u64 t, %1; cvt.u32.u64 %0, t; }" : "=r"(a) : "l"(p));
    return a;
}
__device__ __forceinline__ void cp_async16(unsigned dst, const void* src, int src_bytes) {
    asm volatile("cp.async.cg.shared.global [%0], [%1], 16, %2;"
                 :: "r"(dst), "l"(src), "r"(src_bytes) : "memory");
}
#define CP_COMMIT() asm volatile("cp.async.commit_group;" ::: "memory")
#define CP_WAIT0()  asm volatile("cp.async.wait_group 0;" ::: "memory")

/* ---------------- bulk zero ---------------- */
__global__ void zero_kernel(int* degr, int nr, int* degc, int nc,
                            float* pool, long np, int* cnt, int* work) {
    long total = (long)nr + nc + np + nr + 1;
    for (long i = (long)blockIdx.x * blockDim.x + threadIdx.x; i < total;
         i += (long)gridDim.x * blockDim.x) {
        if (i < nr) degr[i] = 0;
        else if (i < (long)nr + nc) degc[i - nr] = 0;
        else if (i < (long)nr + nc + np) pool[i - nr - nc] = 0.f;
        else if (i < (long)nr + nc + np + nr) cnt[i - nr - nc - np] = 0;
        else *work = 0;
    }
}

/* ---------------- fused CSR build (both graphs) ---------------- */
__global__ void deg_both(const int* __restrict__ eir, int Er, int nr, int* degr,
                         const int* __restrict__ eic, int Ec, int nc, int* degc) {
    int i = blockIdx.x * blockDim.x + threadIdx.x;
    int totr = Er + nr;
    if (i < totr) {
        int dst = (i < Er) ? eir[Er + i] : (i - Er);
        atomicAdd(&degr[dst], 1);
    } else {
        int j = i - totr;
        if (j >= Ec + nc) return;
        int dst = (j < Ec) ? eic[Ec + j] : (j - Ec);
        atomicAdd(&degc[dst], 1);
    }
}

__device__ __forceinline__ int blockscan4(const int* __restrict__ deg, int base, int n,
                                          int v[4], int* warpsums) {
    int tid = threadIdx.x, lane = tid & 31, w = tid >> 5;
    int s = 0;
#pragma unroll
    for (int q = 0; q < 4; q++) {
        int i = base + tid * 4 + q;
        v[q] = (i < n) ? deg[i] : 0;
        s += v[q];
    }
    int x = s;
    for (int o = 1; o < 32; o <<= 1) {
        int y = __shfl_up_sync(0xffffffffu, x, o);
        if (lane >= o) x += y;
    }
    if (lane == 31) warpsums[w] = x;
    __syncthreads();
    if (w == 0) {
        int t = warpsums[lane & 7];
        for (int o = 1; o < 8; o <<= 1) {
            int y = __shfl_up_sync(0xffffffffu, t, o);
            if ((lane & 7) >= o) t += y;
        }
        if (lane < 8) warpsums[lane] = t;
    }
    __syncthreads();
    return (w > 0 ? warpsums[w - 1] : 0) + x - s;
}

__global__ void scan_p1_both(const int* __restrict__ degr, int nr, int ncr, int* bsumr,
                             const int* __restrict__ degc, int nc, int* bsumc) {
    __shared__ int warpsums[32];
    int v[4];
    if ((int)blockIdx.x < ncr) {
        int excl = blockscan4(degr, blockIdx.x * SCHUNK, nr, v, warpsums);
        if (threadIdx.x == 255) bsumr[blockIdx.x] = excl + v[0] + v[1] + v[2] + v[3];
    } else {
        int b = blockIdx.x - ncr;
        int excl = blockscan4(degc, b * SCHUNK, nc, v, warpsums);
        if (threadIdx.x == 255) bsumc[b] = excl + v[0] + v[1] + v[2] + v[3];
    }
}

__device__ __forceinline__ void warp_exscan(int* bsum, int nb, int n, int* rowptr) {
    int lane = threadIdx.x & 31;
    int acc = 0;
    for (int b = 0; b < nb; b += 32) {
        int v = (b + lane < nb) ? bsum[b + lane] : 0;
        int x = v;
        for (int o = 1; o < 32; o <<= 1) {
            int y = __shfl_up_sync(0xffffffffu, x, o);
            if (lane >= o) x += y;
        }
        if (b + lane < nb) bsum[b + lane] = acc + x - v;
        int tot = __shfl_sync(0xffffffffu, x, 31);
        acc += tot;
    }
    if (lane == 0) rowptr[n] = acc;
}

__global__ void scan_p2_both(int* bsumr, int nbr, int nr, int* rowptrr,
                             int* bsumc, int nbc, int nc, int* rowptrc) {
    if (blockIdx.x == 0) warp_exscan(bsumr, nbr, nr, rowptrr);
    else                 warp_exscan(bsumc, nbc, nc, rowptrc);
}

__global__ void scan_p3_both(const int* __restrict__ degr, int nr, int ncr,
                             const int* __restrict__ bsumr, int* rowptrr, int* wpr,
                             const int* __restrict__ degc, int nc,
                             const int* __restrict__ bsumc, int* rowptrc, int* wpc) {
    __shared__ int warpsums[32];
    int v[4];
    const int* deg; const int* bsum; int* rowptr; int* wp; int n, b;
    if ((int)blockIdx.x < ncr) { deg = degr; bsum = bsumr; rowptr = rowptrr; wp = wpr; n = nr; b = blockIdx.x; }
    else { deg = degc; bsum = bsumc; rowptr = rowptrc; wp = wpc; n = nc; b = blockIdx.x - ncr; }
    int base = b * SCHUNK;
    int excl = blockscan4(deg, base, n, v, warpsums) + bsum[b];
#pragma unroll
    for (int q = 0; q < 4; q++) {
        int i = base + threadIdx.x * 4 + q;
        if (i < n) { rowptr[i] = excl; wp[i] = excl; }
        excl += v[q];
    }
}

__global__ void scatter_both(const int* __restrict__ eir, int Er, int nr, int* wpr, int* srcr,
                             const int* __restrict__ eic, int Ec, int nc, int* wpc, int* srcc) {
    int i = blockIdx.x * blockDim.x + threadIdx.x;
    int totr = Er + nr;
    if (i < totr) {
        int src = (i < Er) ? eir[i] : (i - Er);
        int dst = (i < Er) ? eir[Er + i] : (i - Er);
        int pos = atomicAdd(&wpr[dst], 1);
        srcr[pos] = src;
    } else {
        int j = i - totr;
        if (j >= Ec + nc) return;
        int src = (j < Ec) ? eic[j] : (j - Ec);
        int dst = (j < Ec) ? eic[Ec + j] : (j - Ec);
        int pos = atomicAdd(&wpc[dst], 1);
        srcc[pos] = src;
    }
}

/* ----- layer-1 linear (d_in=6) + dots: warp per node, no block barriers ----- */
__device__ __forceinline__ void lin1_warp(const float* __restrict__ x, const float* __restrict__ W,
                                          const float* __restrict__ a_s, const float* __restrict__ a_d,
                                          float* __restrict__ h, float* __restrict__ es,
                                          float* __restrict__ ed, int node, int lane) {
    float xv = (lane < 6) ? x[node * 6 + lane] : 0.f;
    float xk[6];
#pragma unroll
    for (int k = 0; k < 6; k++) xk[k] = __shfl_sync(0xffffffffu, xv, k);
    float acc[4];
#pragma unroll
    for (int q = 0; q < 4; q++) {
        int f = lane + 32 * q;
        float a = 0.f;
#pragma unroll
        for (int k = 0; k < 6; k++) a += xk[k] * W[k * HID + f];
        acc[q] = a;
        h[node * HID + f] = a;
    }
    float r1 = 0.f, r2 = 0.f;
#pragma unroll
    for (int q = 0; q < 4; q++) {
        int f = lane + 32 * q;
        r1 += acc[q] * a_s[f];
        r2 += acc[q] * a_d[f];
    }
    for (int o = 16; o > 0; o >>= 1) {
        r1 += __shfl_down_sync(0xffffffffu, r1, o);
        r2 += __shfl_down_sync(0xffffffffu, r2, o);
    }
    if (lane == 0) { es[node] = r1; ed[node] = r2; }
}

__global__ void lin1_both(const float* xr, const float* Wr, const float* asr, const float* adr,
                          float* hr, float* esr, float* edr, int nr,
                          const float* xc, const float* Wc, const float* asc, const float* adc,
                          float* hc, float* esc, float* edc, int nc) {
    int wrp = (blockIdx.x * blockDim.x + threadIdx.x) >> 5;
    int lane = threadIdx.x & 31;
    if (wrp < nr)
        lin1_warp(xr, Wr, asr, adr, hr, esr, edr, wrp, lane);
    else if (wrp < nr + nc)
        lin1_warp(xc, Wc, asc, adc, hc, esc, edc, wrp - nr, lane);
}

/* ------- layer-2 persistent GEMM + fused dots, both ------- */
__global__ void __launch_bounds__(256)
gemm128_both(const float* __restrict__ xr, const float* __restrict__ Wr,
             const float* __restrict__ asr, const float* __restrict__ adr,
             float* __restrict__ hor, float* __restrict__ esr, float* __restrict__ edr,
             int nr, int splitB,
             const float* __restrict__ xc, const float* __restrict__ Wc,
             const float* __restrict__ asc, const float* __restrict__ adc,
             float* __restrict__ hoc, float* __restrict__ esc, float* __restrict__ edc,
             int nc) {
    extern __shared__ float sm[];
    float* Ws = sm;
    float* xs = sm + 128 * 128;
    int t = threadIdx.x, tx = t & 15, ty = t >> 4;

    const float *x, *W, *a_s, *a_d;
    float *h, *es, *ed;
    int n, b0, gs;
    if ((int)blockIdx.x < splitB) {
        x = xr; W = Wr; a_s = asr; a_d = adr; h = hor; es = esr; ed = edr;
        n = nr; b0 = blockIdx.x; gs = splitB;
    } else {
        x = xc; W = Wc; a_s = asc; a_d = adc; h = hoc; es = esc; ed = edc;
        n = nc; b0 = blockIdx.x - splitB; gs = gridDim.x - splitB;
    }

    for (int i = t * 4; i < 128 * 128; i += 1024)
        *(float4*)&Ws[i] = *(const float4*)&W[i];

    float sv[8], dv[8];
#pragma unroll
    for (int j = 0; j < 8; j++) { sv[j] = a_s[tx * 8 + j]; dv[j] = a_d[tx * 8 + j]; }

    for (int nb = b0 * 64; nb < n; nb += gs * 64) {
        __syncthreads();
#pragma unroll
        for (int m = 0; m < 8; m++) {
            int idx = t + m * 256;
            int row = idx >> 5, c4 = idx & 31;
            float4 v = make_float4(0.f, 0.f, 0.f, 0.f);
            if (nb + row < n) v = ((const float4*)x)[(size_t)(nb + row) * 32 + c4];
            *(float4*)&xs[row * LDX + c4 * 4] = v;
        }
        __syncthreads();
        float acc[4][8];
#pragma unroll
        for (int i = 0; i < 4; i++)
#pragma unroll
            for (int j = 0; j < 8; j++) acc[i][j] = 0.f;
#pragma unroll 4
        for (int k = 0; k < 128; k++) {
            float a0 = xs[(ty * 4 + 0) * LDX + k];
            float a1 = xs[(ty * 4 + 1) * LDX + k];
            float a2 = xs[(ty * 4 + 2) * LDX + k];
            float a3 = xs[(ty * 4 + 3) * LDX + k];
            float4 b0v = *(const float4*)&Ws[k * 128 + tx * 8];
            float4 b1v = *(const float4*)&Ws[k * 128 + tx * 8 + 4];
            float bb[8] = {b0v.x, b0v.y, b0v.z, b0v.w, b1v.x, b1v.y, b1v.z, b1v.w};
#pragma unroll
            for (int j = 0; j < 8; j++) {
                acc[0][j] += a0 * bb[j];
                acc[1][j] += a1 * bb[j];
                acc[2][j] += a2 * bb[j];
                acc[3][j] += a3 * bb[j];
            }
        }
#pragma unroll
        for (int i = 0; i < 4; i++) {
            int node = nb + ty * 4 + i;
            if (node < n) {
                *(float4*)&h[(size_t)node * 128 + tx * 8]     = make_float4(acc[i][0], acc[i][1], acc[i][2], acc[i][3]);
                *(float4*)&h[(size_t)node * 128 + tx * 8 + 4] = make_float4(acc[i][4], acc[i][5], acc[i][6], acc[i][7]);
            }
            float ps = 0.f, pd = 0.f;
#pragma unroll
            for (int j = 0; j < 8; j++) { ps += acc[i][j] * sv[j]; pd += acc[i][j] * dv[j]; }
            for (int o = 8; o > 0; o >>= 1) {
                ps += __shfl_down_sync(0xffffffffu, ps, o, 16);
                pd += __shfl_down_sync(0xffffffffu, pd, o, 16);
            }
            if (tx == 0 && node < n) { es[node] = ps; ed[node] = pd; }
        }
    }
}

/* --------- softmax + aggregate, both --------- */
__device__ __forceinline__ void agg_body(const float* __restrict__ h, const float* __restrict__ bias,
                                         const int* __restrict__ rowptr, const int* __restrict__ csr_src,
                                         const float* __restrict__ es, const float* __restrict__ ed,
                                         float* __restrict__ out, __half* __restrict__ outh,
                                         float* __restrict__ rn, int node, int lane) {
    int b0 = rowptr[node], b1 = rowptr[node + 1];
    float edn = ed[node];

    float m = -FLT_MAX;
    for (int j = b0 + lane; j < b1; j += 32) {
        float e = es[csr_src[j]] + edn;
        e = (e > 0.f) ? e : 0.2f * e;
        m = fmaxf(m, e);
    }
    for (int o = 16; o > 0; o >>= 1) m = fmaxf(m, __shfl_down_sync(0xffffffffu, m, o));
    m = __shfl_sync(0xffffffffu, m, 0);

    float s = 0.f;
    for (int j = b0 + lane; j < b1; j += 32) {
        float e = es[csr_src[j]] + edn;
        e = (e > 0.f) ? e : 0.2f * e;
        s += __expf(e - m);
    }
    for (int o = 16; o > 0; o >>= 1) s += __shfl_down_sync(0xffffffffu, s, o);
    s = __shfl_sync(0xffffffffu, s, 0);
    float inv = 1.f / fmaxf(s, 1e-16f);

    const float4* h4 = (const float4*)h;
    float4 acc = make_float4(0.f, 0.f, 0.f, 0.f);
    for (int j = b0; j < b1; j++) {
        int src = csr_src[j];
        float e = es[src] + edn;
        e = (e > 0.f) ? e : 0.2f * e;
        float w = __expf(e - m) * inv;
        float4 hv = h4[src * 32 + lane];
        acc.x += w * hv.x; acc.y += w * hv.y; acc.z += w * hv.z; acc.w += w * hv.w;
    }
    float4 bb = ((const float4*)bias)[lane];
    acc.x = fmaxf(acc.x + bb.x, 0.f); acc.y = fmaxf(acc.y + bb.y, 0.f);
    acc.z = fmaxf(acc.z + bb.z, 0.f); acc.w = fmaxf(acc.w + bb.w, 0.f);
    ((float4*)out)[node * 32 + lane] = acc;

    if (outh) {
        __half2 p0 = __halves2half2(__float2half_rn(acc.x), __float2half_rn(acc.y));
        __half2 p1 = __halves2half2(__float2half_rn(acc.z), __float2half_rn(acc.w));
        ((__half2*)outh)[node * 64 + lane * 2]     = p0;
        ((__half2*)outh)[node * 64 + lane * 2 + 1] = p1;
    }
    if (rn) {
        float q = acc.x * acc.x + acc.y * acc.y + acc.z * acc.z + acc.w * acc.w;
        for (int o = 16; o > 0; o >>= 1) q += __shfl_down_sync(0xffffffffu, q, o);
        if (lane == 0) rn[node] = q;
    }
}

__global__ void agg_both(const float* hrI, const float* br, const int* rpr, const int* srcr,
                         const float* esr, const float* edr, float* outr, __half* outhr,
                         float* rnr, int nr,
                         const float* hcI, const float* bc, const int* rpc, const int* srcc,
                         const float* esc, const float* edc, float* outc, __half* outhc,
                         float* rnc, int nc) {
    int wrp = (blockIdx.x * blockDim.x + threadIdx.x) >> 5;
    int lane = threadIdx.x & 31;
    if (wrp < nr)
        agg_body(hrI, br, rpr, srcr, esr, edr, outr, outhr, rnr, wrp, lane);
    else if (wrp < nr + nc)
        agg_body(hcI, bc, rpc, srcc, esc, edc, outc, outhc, rnc, wrp - nr, lane);
}

/* ---------------- KNN selection helpers ---------------- */
__device__ __forceinline__ bool bet(float v, int id, float v2, int id2) {
    return v < v2 || (v == v2 && id < id2);
}
__device__ __forceinline__ void top3_insert(float v, int id, float tv[3], int ti[3]) {
    if (!bet(v, id, tv[2], ti[2])) return;
    tv[2] = v; ti[2] = id;
    if (bet(tv[2], ti[2], tv[1], ti[1])) {
        float f = tv[1]; tv[1] = tv[2]; tv[2] = f;
        int q = ti[1]; ti[1] = ti[2]; ti[2] = q;
    }
    if (bet(tv[1], ti[1], tv[0], ti[0])) {
        float f = tv[0]; tv[0] = tv[1]; tv[1] = f;
        int q = ti[0]; ti[0] = ti[1]; ti[1] = q;
    }
}
#define T8SW(a, b) \
    if (bet(tv[b], ti[b], tv[a], ti[a])) { \
        float f_ = tv[a]; tv[a] = tv[b]; tv[b] = f_; \
        int q_ = ti[a]; ti[a] = ti[b]; ti[b] = q_; }
__device__ __forceinline__ void top8_insert(float s, int id, float tv[8], int ti[8]) {
    if (!bet(s, id, tv[7], ti[7])) return;
    tv[7] = s; ti[7] = id;
    T8SW(6, 7) T8SW(5, 6) T8SW(4, 5) T8SW(3, 4) T8SW(2, 3) T8SW(1, 2) T8SW(0, 1)
}

/* Persistent wmma KNN: A fragments cached in registers per c-tile. */
__global__ void __launch_bounds__(256, 2)
knn_wmma_kernel(const __half* __restrict__ hch, const __half* __restrict__ hrh,
                const float* __restrict__ rn,
                int n_c, int n_r, int n_rtiles, int tiles_per, int n_items,
                float* __restrict__ pv, int* __restrict__ pi) {
    extern __shared__ char dsm[];
    __half* As  = (__half*)dsm;
    __half* Bs  = As + 128 * LDT;
    float*  scr = (float*)(Bs + 2 * BTILE * LDT);
    __shared__ int s_item;

    int tid = threadIdx.x, wid = tid >> 5, lane = tid & 31;
    int crow = lane & 15, chalf = lane >> 4;
    float* myscr = scr + wid * 256;
    unsigned bbase = smem_u32(Bs);

    int row0 = tid >> 4, k80 = tid & 15;
    int prev_ct = -1;
    wmma::fragment<wmma::matrix_a, 16, 16, 16, __half, wmma::row_major> af[8];

    for (;;) {
        __syncthreads();
        if (tid == 0) s_item = atomicAdd(&g_work, 1);
        __syncthreads();
        int item = s_item;
        if (item >= n_items) break;
        int ct = item / RSPLIT;
        int rs = item - ct * RSPLIT;
        int cbase = ct * 128;
        int t0 = rs * tiles_per;
        int t1 = min(t0 + tiles_per, n_rtiles);
        int my_c = cbase + wid * 16 + crow;

        float tv[8]; int ti[8];
#pragma unroll
        for (int s = 0; s < 8; s++) { tv[s] = FLT_MAX; ti[s] = 0x7fffffff; }

        if (t0 < t1) {
            if (ct != prev_ct) {
#pragma unroll
                for (int m = 0; m < 8; m++) {
                    int idx = tid + m * 256;
                    int row = idx >> 4, k8 = idx & 15;
                    int c = cbase + row;
                    uint4 v = make_uint4(0, 0, 0, 0);
                    if (c < n_c) v = ((const uint4*)hch)[c * 16 + k8];
                    *(uint4*)&As[row * LDT + k8 * 8] = v;
                }
                __syncthreads();
#pragma unroll
                for (int k = 0; k < 8; k++)
                    wmma::load_matrix_sync(af[k], &As[(wid * 16) * LDT + k * 16], LDT);
                prev_ct = ct;
            }

            {
                int rbase = t0 * BTILE;
#pragma unroll
                for (int m = 0; m < 4; m++) {
                    int row = row0 + m * 16;
                    int r = rbase + row;
                    int ok = (r < n_r);
                    const void* src = hrh + (size_t)(ok ? r : 0) * 128 + k80 * 8;
                    cp_async16(bbase + (row * LDT + k80 * 8) * 2, src, ok ? 16 : 0);
                }
                CP_COMMIT();
            }

            for (int tt = t0; tt < t1; tt++) {
                int cur = (tt - t0) & 1;
                CP_WAIT0();
                __syncthreads();
                if (tt + 1 < t1) {
                    int nxt = cur ^ 1;
                    int rbase2 = (tt + 1) * BTILE;
#pragma unroll
                    for (int m = 0; m < 4; m++) {
                        int row = row0 + m * 16;
                        int r = rbase2 + row;
                        int ok = (r < n_r);
                        const void* src = hrh + (size_t)(ok ? r : 0) * 128 + k80 * 8;
                        cp_async16(bbase + (nxt * BTILE * LDT + row * LDT + k80 * 8) * 2, src, ok ? 16 : 0);
                    }
                    CP_COMMIT();
                }

                const __half* Bc = Bs + cur * BTILE * LDT;
                int rbase = tt * BTILE;

                wmma::fragment<wmma::accumulator, 16, 16, 16, float> acc[4];
#pragma unroll
                for (int f = 0; f < 4; f++) wmma::fill_fragment(acc[f], 0.f);
#pragma unroll
                for (int k = 0; k < 8; k++) {
#pragma unroll
                    for (int f = 0; f < 4; f++) {
                        wmma::fragment<wmma::matrix_b, 16, 16, 16, __half, wmma::col_major> bf;
                        wmma::load_matrix_sync(bf, &Bc[(f * 16) * LDT + k * 16], LDT);
                        wmma::mma_sync(acc[f], af[k], bf, acc[f]);
                    }
                }

#pragma unroll
                for (int f = 0; f < 4; f++) {
                    wmma::store_matrix_sync(myscr, acc[f], 16, wmma::mem_row_major);
                    __syncwarp();
                    int cb = f * 16 + chalf * 8;
#pragma unroll
                    for (int j = 0; j < 8; j++) {
                        int r = rbase + cb + j;
                        float rv = (r < n_r) ? rn[r] : 1e30f;
                        float d = myscr[crow * 16 + chalf * 8 + j];
                        top8_insert(fmaf(-2.f, d, rv), r, tv, ti);
                    }
                    __syncwarp();
                }
            }
        }

        if (my_c < n_c) {
            int ebase = (rs * 2 + chalf) * 8;
#pragma unroll
            for (int s = 0; s < 8; s++) {
                pv[(ebase + s) * MAX_NC_PAD + my_c] = tv[s];
                pi[(ebase + s) * MAX_NC_PAD + my_c] = ti[s];
            }
        }
    }
}

__global__ void merge8_kernel(const float* __restrict__ pv, const int* __restrict__ pi,
                              int n_c, int n_r, int* __restrict__ cand) {
    int c = blockIdx.x * blockDim.x + threadIdx.x;
    if (c >= n_c) return;
    float tv[8]; int ti[8];
#pragma unroll
    for (int s = 0; s < 8; s++) { tv[s] = FLT_MAX; ti[s] = 0x7fffffff; }
    for (int e = 0; e < NPART; e++) {
        int id = pi[e * MAX_NC_PAD + c];
        if ((unsigned)id < (unsigned)n_r)
            top8_insert(pv[e * MAX_NC_PAD + c], id, tv, ti);
    }
#pragma unroll
    for (int j = 0; j < 8; j++) cand[c * TOPP + j] = ti[j];
}

__global__ void rescore_kernel(const int* __restrict__ cand, const float* __restrict__ hc,
                               const float* __restrict__ hr, const float* __restrict__ rn,
                               int n_c, int n_r, float* __restrict__ sc) {
    int gw = (blockIdx.x * blockDim.x + threadIdx.x) >> 5;
    int lane = threadIdx.x & 31;
    if (gw >= n_c * TOPP) return;
    int c = gw / TOPP, j = gw - c * TOPP;
    int id = cand[c * TOPP + j];
    float s = FLT_MAX;
    if ((unsigned)id < (unsigned)n_r) {
        float4 a = ((const float4*)hc)[c * 32 + lane];
        float4 b = ((const float4*)hr)[id * 32 + lane];
        float d = a.x * b.x + a.y * b.y + a.z * b.z + a.w * b.w;
        for (int o = 16; o > 0; o >>= 1) d += __shfl_down_sync(0xffffffffu, d, o);
        s = rn[id] - 2.f * d;
    }
    if (lane == 0) sc[c * TOPP + j] = s;
}

__global__ void final3_kernel(const float* __restrict__ sc, const int* __restrict__ cand,
                              int n_c, int n_r, int* __restrict__ nn) {
    int c = blockIdx.x * blockDim.x + threadIdx.x;
    if (c >= n_c) return;
    float bv[3] = {FLT_MAX, FLT_MAX, FLT_MAX};
    int   bi[3] = {0x7fffffff, 0x7fffffff, 0x7fffffff};
#pragma unroll
    for (int j = 0; j < TOPP; j++) {
        int id = cand[c * TOPP + j];
        if ((unsigned)id < (unsigned)n_r)
            top3_insert(sc[c * TOPP + j], id, bv, bi);
    }
    nn[c * 3 + 0] = bi[0]; nn[c * 3 + 1] = bi[1]; nn[c * 3 + 2] = bi[2];
}

/* ---------------- pooling + decode ---------------- */
__global__ void assign_kernel(const float* __restrict__ hc, const int* __restrict__ nn,
                              float* __restrict__ pool, int* __restrict__ cnt, int n_c) {
    int g = blockIdx.x * blockDim.x + threadIdx.x;
    int w = g >> 5, lane = g & 31;
    if (w >= n_c * KNN_K) return;
    int c = w / KNN_K;
    int idx = nn[w];
    if (lane == 0) atomicAdd(&cnt[idx], 1);
    float4 hv = ((const float4*)hc)[c * 32 + lane];
    atomicAdd(&pool[idx * HID + lane * 4 + 0], hv.x);
    atomicAdd(&pool[idx * HID + lane * 4 + 1], hv.y);
    atomicAdd(&pool[idx * HID + lane * 4 + 2], hv.z);
    atomicAdd(&pool[idx * HID + lane * 4 + 3], hv.w);
}

__global__ void decode_kernel(const float* __restrict__ hr, const float* __restrict__ pool,
                              const int* __restrict__ cnt, const float* __restrict__ Wd,
                              const float* __restrict__ bd, float* __restrict__ out, int n) {
    int i = (blockIdx.x * blockDim.x + threadIdx.x) >> 5;
    int lane = threadIdx.x & 31;
    if (i >= n) return;
    float inv = 1.f / fmaxf((float)cnt[i], 1.f);
    float a0 = 0.f, a1 = 0.f, a2 = 0.f;
    for (int f = lane; f < HID; f += 32) {
        float v = hr[i * HID + f];
        a0 += v * Wd[f * 3 + 0]; a1 += v * Wd[f * 3 + 1]; a2 += v * Wd[f * 3 + 2];
        float p = pool[i * HID + f] * inv;
        a0 += p * Wd[(HID + f) * 3 + 0]; a1 += p * Wd[(HID + f) * 3 + 1]; a2 += p * Wd[(HID + f) * 3 + 2];
    }
    for (int o = 16; o > 0; o >>= 1) {
        a0 += __shfl_down_sync(0xffffffffu, a0, o);
        a1 += __shfl_down_sync(0xffffffffu, a1, o);
        a2 += __shfl_down_sync(0xffffffffu, a2, o);
    }
    if (lane == 0) {
        out[i * 3 + 0] = a0 + bd[0];
        out[i * 3 + 1] = a1 + bd[1];
        out[i * 3 + 2] = a2 + bd[2];
    }
}

/* ---------------- host ---------------- */
extern "C" void kernel_launch(void* const* d_in, const int* in_sizes, int n_in,
                              void* d_out, int out_size) {
    const float* x_r  = (const float*)d_in[0];
    const float* x_c  = (const float*)d_in[1];
    const int*   ei_r = (const int*)d_in[2];
    const int*   ei_c = (const int*)d_in[3];
    const float* W_r1 = (const float*)d_in[5];
    const float* as_r1 = (const float*)d_in[6];
    const float* ad_r1 = (const float*)d_in[7];
    const float* b_r1  = (const float*)d_in[8];
    const float* W_r2 = (const float*)d_in[9];
    const float* as_r2 = (const float*)d_in[10];
    const float* ad_r2 = (const float*)d_in[11];
    const float* b_r2  = (const float*)d_in[12];
    const float* W_c1 = (const float*)d_in[13];
    const float* as_c1 = (const float*)d_in[14];
    const float* ad_c1 = (const float*)d_in[15];
    const float* b_c1  = (const float*)d_in[16];
    const float* W_c2 = (const float*)d_in[17];
    const float* as_c2 = (const float*)d_in[18];
    const float* ad_c2 = (const float*)d_in[19];
    const float* b_c2  = (const float*)d_in[20];
    const float* W_dec = (const float*)d_in[21];
    const float* b_dec = (const float*)d_in[22];
    float* out = (float*)d_out;

    int n_r = in_sizes[0] / 6;
    int n_c = in_sizes[1] / 6;
    int E_r = in_sizes[2] / 2;
    int E_c = in_sizes[3] / 2;

    float *lin, *linc, *hr1, *hr, *hc1, *hc, *es, *ed, *esc, *edc, *rnorm, *pv, *pool, *sc;
    __half *hch, *hrh;
    int *degr, *degc, *rowptr, *rowptrc, *wp, *wpc, *bsum, *bsumc;
    int *csr_src, *csr_srcc, *pi, *nn, *cnt, *work, *cand;
    cudaGetSymbolAddress((void**)&lin, g_lin);
    cudaGetSymbolAddress((void**)&linc, g_linc);
    cudaGetSymbolAddress((void**)&hr1, g_hr1);
    cudaGetSymbolAddress((void**)&hr,  g_hr);
    cudaGetSymbolAddress((void**)&hc1, g_hc1);
    cudaGetSymbolAddress((void**)&hc,  g_hc);
    cudaGetSymbolAddress((void**)&es,  g_es);
    cudaGetSymbolAddress((void**)&ed,  g_ed);
    cudaGetSymbolAddress((void**)&esc, g_esc);
    cudaGetSymbolAddress((void**)&edc, g_edc);
    cudaGetSymbolAddress((void**)&degr, g_degr);
    cudaGetSymbolAddress((void**)&degc, g_degc);
    cudaGetSymbolAddress((void**)&rowptr, g_rowptr);
    cudaGetSymbolAddress((void**)&rowptrc, g_rowptrc);
    cudaGetSymbolAddress((void**)&wp,  g_wp);
    cudaGetSymbolAddress((void**)&wpc, g_wpc);
    cudaGetSymbolAddress((void**)&bsum, g_bsum);
    cudaGetSymbolAddress((void**)&bsumc, g_bsumc);
    cudaGetSymbolAddress((void**)&csr_src, g_csr_src);
    cudaGetSymbolAddress((void**)&csr_srcc, g_csr_srcc);
    cudaGetSymbolAddress((void**)&rnorm, g_rnorm);
    cudaGetSymbolAddress((void**)&hch, g_hch);
    cudaGetSymbolAddress((void**)&hrh, g_hrh);
    cudaGetSymbolAddress((void**)&pv, g_pv);
    cudaGetSymbolAddress((void**)&pi, g_pi);
    cudaGetSymbolAddress((void**)&cand, g_cand);
    cudaGetSymbolAddress((void**)&sc, g_sc);
    cudaGetSymbolAddress((void**)&nn, g_nn);
    cudaGetSymbolAddress((void**)&pool, g_pool);
    cudaGetSymbolAddress((void**)&cnt, g_cnt);
    cudaGetSymbolAddress((void**)&work, g_work);

    size_t gemm_smem = (size_t)(128 * 128 + 64 * LDX) * sizeof(float);
    cudaFuncSetAttribute(gemm128_both, cudaFuncAttributeMaxDynamicSharedMemorySize,
                         (int)gemm_smem);

    {
        long np = (long)n_r * HID;
        long total = (long)n_r + n_c + np + n_r + 1;
        int zb = (int)((total + 255) / 256);
        if (zb > 4096) zb = 4096;
        zero_kernel<<<zb, 256>>>(degr, n_r, degc, n_c, pool, np, cnt, work);
    }

    int totr = E_r + n_r, totc = E_c + n_c;
    int ncr = (n_r + SCHUNK - 1) / SCHUNK;
    int ncc = (n_c + SCHUNK - 1) / SCHUNK;

    deg_both<<<(totr + totc + 255) / 256, 256>>>(ei_r, E_r, n_r, degr, ei_c, E_c, n_c, degc);
    scan_p1_both<<<ncr + ncc, 256>>>(degr, n_r, ncr, bsum, degc, n_c, bsumc);
    scan_p2_both<<<2, 32>>>(bsum, ncr, n_r, rowptr, bsumc, ncc, n_c, rowptrc);
    scan_p3_both<<<ncr + ncc, 256>>>(degr, n_r, ncr, bsum, rowptr, wp,
                                     degc, n_c, bsumc, rowptrc, wpc);
    scatter_both<<<(totr + totc + 255) / 256, 256>>>(ei_r, E_r, n_r, wp, csr_src,
                                                     ei_c, E_c, n_c, wpc, csr_srcc);

    lin1_both<<<(n_r + n_c + 7) / 8, 256>>>(x_r, W_r1, as_r1, ad_r1, hr1, es, ed, n_r,
                                            x_c, W_c1, as_c1, ad_c1, hc1, esc, edc, n_c);
    agg_both<<<(n_r + n_c + 7) / 8, 256>>>(hr1, b_r1, rowptr, csr_src, es, ed,
                                           lin, (__half*)0, (float*)0, n_r,
                                           hc1, b_c1, rowptrc, csr_srcc, esc, edc,
                                           linc, (__half*)0, (float*)0, n_c);
    {
        int splitB = (int)((long)152 * n_r / (n_r + n_c));
        if (splitB < 1) splitB = 1;
        if (splitB > 151) splitB = 151;
        gemm128_both<<<152, 256, gemm_smem>>>(lin, W_r2, as_r2, ad_r2, hr1, es, ed, n_r, splitB,
                                              linc, W_c2, as_c2, ad_c2, hc1, esc, edc, n_c);
    }
    agg_both<<<(n_r + n_c + 7) / 8, 256>>>(hr1, b_r2, rowptr, csr_src, es, ed,
                                           hr, hrh, rnorm, n_r,
                                           hc1, b_c2, rowptrc, csr_srcc, esc, edc,
                                           hc, hch, (float*)0, n_c);

    /* KNN */
    int n_rtiles = (n_r + BTILE - 1) / BTILE;
    int tiles_per = (n_rtiles + RSPLIT - 1) / RSPLIT;
    int nct = (n_c + 127) / 128;
    int n_items = nct * RSPLIT;
    size_t knn_smem = (size_t)((128 + 2 * BTILE) * LDT) * sizeof(__half)
                    + (size_t)(8 * 256) * sizeof(float);
    cudaFuncSetAttribute(knn_wmma_kernel, cudaFuncAttributeMaxDynamicSharedMemorySize,
                         (int)knn_smem);
    knn_wmma_kernel<<<KNN_BLOCKS, 256, knn_smem>>>(hch, hrh, rnorm, n_c, n_r,
                                                   n_rtiles, tiles_per, n_items, pv, pi);
    merge8_kernel<<<(n_c + 127) / 128, 128>>>(pv, pi, n_c, n_r, cand);
    rescore_kernel<<<(n_c * TOPP * 32 + 255) / 256, 256>>>(cand, hc, hr, rnorm, n_c, n_r, sc);
    final3_kernel<<<(n_c + 255) / 256, 256>>>(sc, cand, n_c, n_r, nn);

    assign_kernel<<<(n_c * KNN_K * 32 + 255) / 256, 256>>>(hc, nn, pool, cnt, n_c);
    decode_kernel<<<(n_r * 32 + 255) / 256, 256>>>(hr, pool, cnt, W_dec, b_dec, out, n_r);
}

// round 17
// speedup vs baseline: 1.2965x; 1.2555x over previous
#include <cuda_runtime.h>
#include <cuda_fp16.h>
#include <mma.h>
#include <math.h>
#include <float.h>

using namespace nvcuda;

#define HID 128
#define MAX_N 20000
#define MAX_NC 5000
#define MAX_NC_PAD 5120
#define MAX_E 340000
#define MAX_EC 90000
#define KNN_K 3
#define RSPLIT 15
#define NPART (RSPLIT * 2 * 8)
#define TOPP 8
#define KNN_BLOCKS 304
#define LDT 136
#define LDX 132
#define BTILE 64
#define SCHUNK 1024

__device__ float g_lin [MAX_N * HID];
__device__ float g_linc[MAX_NC * HID];
__device__ float g_hr1 [MAX_N * HID];
__device__ float g_hr  [MAX_N * HID];
__device__ float g_hc1 [MAX_NC * HID];
__device__ float g_hc  [MAX_NC * HID];
__device__ float g_es  [MAX_N];
__device__ float g_ed  [MAX_N];
__device__ float g_esc [MAX_NC];
__device__ float g_edc [MAX_NC];
__device__ int   g_degr[MAX_N];
__device__ int   g_degc[MAX_NC];
__device__ int   g_rowptr [MAX_N + 1];
__device__ int   g_rowptrc[MAX_NC + 1];
__device__ int   g_wp  [MAX_N];
__device__ int   g_wpc [MAX_NC];
__device__ int   g_bsum [64];
__device__ int   g_bsumc[64];
__device__ int   g_csr_src [MAX_E];
__device__ int   g_csr_srcc[MAX_EC];
__device__ float g_rnorm[MAX_N];
__device__ __half g_hch[MAX_NC_PAD * HID];
__device__ __half g_hrh[MAX_N * HID];
__device__ float g_pv [NPART * MAX_NC_PAD];
__device__ int   g_pi [NPART * MAX_NC_PAD];
__device__ float g_pool[MAX_N * HID];
__device__ int   g_cnt [MAX_N];
__device__ int   g_work;

/* ---------------- helpers ---------------- */
__device__ __forceinline__ unsigned smem_u32(const void* p) {
    unsigned a;
    asm("{ .reg .u64 t; cvta.to.shared.u64 t, %1; cvt.u32.u64 %0, t; }" : "=r"(a) : "l"(p));
    return a;
}
__device__ __forceinline__ void cp_async16(unsigned dst, const void* src, int src_bytes) {
    asm volatile("cp.async.cg.shared.global [%0], [%1], 16, %2;"
                 :: "r"(dst), "l"(src), "r"(src_bytes) : "memory");
}
#define CP_COMMIT() asm volatile("cp.async.commit_group;" ::: "memory")
#define CP_WAIT0()  asm volatile("cp.async.wait_group 0;" ::: "memory")

/* ---------------- bulk zero ---------------- */
__global__ void zero_kernel(int* degr, int nr, int* degc, int nc,
                            float* pool, long np, int* cnt, int* work) {
    long total = (long)nr + nc + np + nr + 1;
    for (long i = (long)blockIdx.x * blockDim.x + threadIdx.x; i < total;
         i += (long)gridDim.x * blockDim.x) {
        if (i < nr) degr[i] = 0;
        else if (i < (long)nr + nc) degc[i - nr] = 0;
        else if (i < (long)nr + nc + np) pool[i - nr - nc] = 0.f;
        else if (i < (long)nr + nc + np + nr) cnt[i - nr - nc - np] = 0;
        else *work = 0;
    }
}

/* ---------------- fused CSR build (both graphs) ---------------- */
__global__ void deg_both(const int* __restrict__ eir, int Er, int nr, int* degr,
                         const int* __restrict__ eic, int Ec, int nc, int* degc) {
    int i = blockIdx.x * blockDim.x + threadIdx.x;
    int totr = Er + nr;
    if (i < totr) {
        int dst = (i < Er) ? eir[Er + i] : (i - Er);
        atomicAdd(&degr[dst], 1);
    } else {
        int j = i - totr;
        if (j >= Ec + nc) return;
        int dst = (j < Ec) ? eic[Ec + j] : (j - Ec);
        atomicAdd(&degc[dst], 1);
    }
}

__device__ __forceinline__ int blockscan4(const int* __restrict__ deg, int base, int n,
                                          int v[4], int* warpsums) {
    int tid = threadIdx.x, lane = tid & 31, w = tid >> 5;
    int s = 0;
#pragma unroll
    for (int q = 0; q < 4; q++) {
        int i = base + tid * 4 + q;
        v[q] = (i < n) ? deg[i] : 0;
        s += v[q];
    }
    int x = s;
    for (int o = 1; o < 32; o <<= 1) {
        int y = __shfl_up_sync(0xffffffffu, x, o);
        if (lane >= o) x += y;
    }
    if (lane == 31) warpsums[w] = x;
    __syncthreads();
    if (w == 0) {
        int t = warpsums[lane & 7];
        for (int o = 1; o < 8; o <<= 1) {
            int y = __shfl_up_sync(0xffffffffu, t, o);
            if ((lane & 7) >= o) t += y;
        }
        if (lane < 8) warpsums[lane] = t;
    }
    __syncthreads();
    return (w > 0 ? warpsums[w - 1] : 0) + x - s;
}

__global__ void scan_p1_both(const int* __restrict__ degr, int nr, int ncr, int* bsumr,
                             const int* __restrict__ degc, int nc, int* bsumc) {
    __shared__ int warpsums[32];
    int v[4];
    if ((int)blockIdx.x < ncr) {
        int excl = blockscan4(degr, blockIdx.x * SCHUNK, nr, v, warpsums);
        if (threadIdx.x == 255) bsumr[blockIdx.x] = excl + v[0] + v[1] + v[2] + v[3];
    } else {
        int b = blockIdx.x - ncr;
        int excl = blockscan4(degc, b * SCHUNK, nc, v, warpsums);
        if (threadIdx.x == 255) bsumc[b] = excl + v[0] + v[1] + v[2] + v[3];
    }
}

__device__ __forceinline__ void warp_exscan(int* bsum, int nb, int n, int* rowptr) {
    int lane = threadIdx.x & 31;
    int acc = 0;
    for (int b = 0; b < nb; b += 32) {
        int v = (b + lane < nb) ? bsum[b + lane] : 0;
        int x = v;
        for (int o = 1; o < 32; o <<= 1) {
            int y = __shfl_up_sync(0xffffffffu, x, o);
            if (lane >= o) x += y;
        }
        if (b + lane < nb) bsum[b + lane] = acc + x - v;
        int tot = __shfl_sync(0xffffffffu, x, 31);
        acc += tot;
    }
    if (lane == 0) rowptr[n] = acc;
}

__global__ void scan_p2_both(int* bsumr, int nbr, int nr, int* rowptrr,
                             int* bsumc, int nbc, int nc, int* rowptrc) {
    if (blockIdx.x == 0) warp_exscan(bsumr, nbr, nr, rowptrr);
    else                 warp_exscan(bsumc, nbc, nc, rowptrc);
}

__global__ void scan_p3_both(const int* __restrict__ degr, int nr, int ncr,
                             const int* __restrict__ bsumr, int* rowptrr, int* wpr,
                             const int* __restrict__ degc, int nc,
                             const int* __restrict__ bsumc, int* rowptrc, int* wpc) {
    __shared__ int warpsums[32];
    int v[4];
    const int* deg; const int* bsum; int* rowptr; int* wp; int n, b;
    if ((int)blockIdx.x < ncr) { deg = degr; bsum = bsumr; rowptr = rowptrr; wp = wpr; n = nr; b = blockIdx.x; }
    else { deg = degc; bsum = bsumc; rowptr = rowptrc; wp = wpc; n = nc; b = blockIdx.x - ncr; }
    int base = b * SCHUNK;
    int excl = blockscan4(deg, base, n, v, warpsums) + bsum[b];
#pragma unroll
    for (int q = 0; q < 4; q++) {
        int i = base + threadIdx.x * 4 + q;
        if (i < n) { rowptr[i] = excl; wp[i] = excl; }
        excl += v[q];
    }
}

__global__ void scatter_both(const int* __restrict__ eir, int Er, int nr, int* wpr, int* srcr,
                             const int* __restrict__ eic, int Ec, int nc, int* wpc, int* srcc) {
    int i = blockIdx.x * blockDim.x + threadIdx.x;
    int totr = Er + nr;
    if (i < totr) {
        int src = (i < Er) ? eir[i] : (i - Er);
        int dst = (i < Er) ? eir[Er + i] : (i - Er);
        int pos = atomicAdd(&wpr[dst], 1);
        srcr[pos] = src;
    } else {
        int j = i - totr;
        if (j >= Ec + nc) return;
        int src = (j < Ec) ? eic[j] : (j - Ec);
        int dst = (j < Ec) ? eic[Ec + j] : (j - Ec);
        int pos = atomicAdd(&wpc[dst], 1);
        srcc[pos] = src;
    }
}

/* ----- layer-1 linear (d_in=6) + dots: warp per node ----- */
__device__ __forceinline__ void lin1_warp(const float* __restrict__ x, const float* __restrict__ W,
                                          const float* __restrict__ a_s, const float* __restrict__ a_d,
                                          float* __restrict__ h, float* __restrict__ es,
                                          float* __restrict__ ed, int node, int lane) {
    float xv = (lane < 6) ? x[node * 6 + lane] : 0.f;
    float xk[6];
#pragma unroll
    for (int k = 0; k < 6; k++) xk[k] = __shfl_sync(0xffffffffu, xv, k);
    float acc[4];
#pragma unroll
    for (int q = 0; q < 4; q++) {
        int f = lane + 32 * q;
        float a = 0.f;
#pragma unroll
        for (int k = 0; k < 6; k++) a += xk[k] * W[k * HID + f];
        acc[q] = a;
        h[node * HID + f] = a;
    }
    float r1 = 0.f, r2 = 0.f;
#pragma unroll
    for (int q = 0; q < 4; q++) {
        int f = lane + 32 * q;
        r1 += acc[q] * a_s[f];
        r2 += acc[q] * a_d[f];
    }
    for (int o = 16; o > 0; o >>= 1) {
        r1 += __shfl_down_sync(0xffffffffu, r1, o);
        r2 += __shfl_down_sync(0xffffffffu, r2, o);
    }
    if (lane == 0) { es[node] = r1; ed[node] = r2; }
}

__global__ void lin1_both(const float* xr, const float* Wr, const float* asr, const float* adr,
                          float* hr, float* esr, float* edr, int nr,
                          const float* xc, const float* Wc, const float* asc, const float* adc,
                          float* hc, float* esc, float* edc, int nc) {
    int wrp = (blockIdx.x * blockDim.x + threadIdx.x) >> 5;
    int lane = threadIdx.x & 31;
    if (wrp < nr)
        lin1_warp(xr, Wr, asr, adr, hr, esr, edr, wrp, lane);
    else if (wrp < nr + nc)
        lin1_warp(xc, Wc, asc, adc, hc, esc, edc, wrp - nr, lane);
}

/* ------- layer-2 persistent GEMM + fused dots, both ------- */
__global__ void __launch_bounds__(256)
gemm128_both(const float* __restrict__ xr, const float* __restrict__ Wr,
             const float* __restrict__ asr, const float* __restrict__ adr,
             float* __restrict__ hor, float* __restrict__ esr, float* __restrict__ edr,
             int nr, int splitB,
             const float* __restrict__ xc, const float* __restrict__ Wc,
             const float* __restrict__ asc, const float* __restrict__ adc,
             float* __restrict__ hoc, float* __restrict__ esc, float* __restrict__ edc,
             int nc) {
    extern __shared__ float sm[];
    float* Ws = sm;
    float* xs = sm + 128 * 128;
    int t = threadIdx.x, tx = t & 15, ty = t >> 4;

    const float *x, *W, *a_s, *a_d;
    float *h, *es, *ed;
    int n, b0, gs;
    if ((int)blockIdx.x < splitB) {
        x = xr; W = Wr; a_s = asr; a_d = adr; h = hor; es = esr; ed = edr;
        n = nr; b0 = blockIdx.x; gs = splitB;
    } else {
        x = xc; W = Wc; a_s = asc; a_d = adc; h = hoc; es = esc; ed = edc;
        n = nc; b0 = blockIdx.x - splitB; gs = gridDim.x - splitB;
    }

    for (int i = t * 4; i < 128 * 128; i += 1024)
        *(float4*)&Ws[i] = *(const float4*)&W[i];

    float sv[8], dv[8];
#pragma unroll
    for (int j = 0; j < 8; j++) { sv[j] = a_s[tx * 8 + j]; dv[j] = a_d[tx * 8 + j]; }

    for (int nb = b0 * 64; nb < n; nb += gs * 64) {
        __syncthreads();
#pragma unroll
        for (int m = 0; m < 8; m++) {
            int idx = t + m * 256;
            int row = idx >> 5, c4 = idx & 31;
            float4 v = make_float4(0.f, 0.f, 0.f, 0.f);
            if (nb + row < n) v = ((const float4*)x)[(size_t)(nb + row) * 32 + c4];
            *(float4*)&xs[row * LDX + c4 * 4] = v;
        }
        __syncthreads();
        float acc[4][8];
#pragma unroll
        for (int i = 0; i < 4; i++)
#pragma unroll
            for (int j = 0; j < 8; j++) acc[i][j] = 0.f;
#pragma unroll 4
        for (int k = 0; k < 128; k++) {
            float a0 = xs[(ty * 4 + 0) * LDX + k];
            float a1 = xs[(ty * 4 + 1) * LDX + k];
            float a2 = xs[(ty * 4 + 2) * LDX + k];
            float a3 = xs[(ty * 4 + 3) * LDX + k];
            float4 b0v = *(const float4*)&Ws[k * 128 + tx * 8];
            float4 b1v = *(const float4*)&Ws[k * 128 + tx * 8 + 4];
            float bb[8] = {b0v.x, b0v.y, b0v.z, b0v.w, b1v.x, b1v.y, b1v.z, b1v.w};
#pragma unroll
            for (int j = 0; j < 8; j++) {
                acc[0][j] += a0 * bb[j];
                acc[1][j] += a1 * bb[j];
                acc[2][j] += a2 * bb[j];
                acc[3][j] += a3 * bb[j];
            }
        }
#pragma unroll
        for (int i = 0; i < 4; i++) {
            int node = nb + ty * 4 + i;
            if (node < n) {
                *(float4*)&h[(size_t)node * 128 + tx * 8]     = make_float4(acc[i][0], acc[i][1], acc[i][2], acc[i][3]);
                *(float4*)&h[(size_t)node * 128 + tx * 8 + 4] = make_float4(acc[i][4], acc[i][5], acc[i][6], acc[i][7]);
            }
            float ps = 0.f, pd = 0.f;
#pragma unroll
            for (int j = 0; j < 8; j++) { ps += acc[i][j] * sv[j]; pd += acc[i][j] * dv[j]; }
            for (int o = 8; o > 0; o >>= 1) {
                ps += __shfl_down_sync(0xffffffffu, ps, o, 16);
                pd += __shfl_down_sync(0xffffffffu, pd, o, 16);
            }
            if (tx == 0 && node < n) { es[node] = ps; ed[node] = pd; }
        }
    }
}

/* --------- softmax + aggregate, both --------- */
__device__ __forceinline__ void agg_body(const float* __restrict__ h, const float* __restrict__ bias,
                                         const int* __restrict__ rowptr, const int* __restrict__ csr_src,
                                         const float* __restrict__ es, const float* __restrict__ ed,
                                         float* __restrict__ out, __half* __restrict__ outh,
                                         float* __restrict__ rn, int node, int lane) {
    int b0 = rowptr[node], b1 = rowptr[node + 1];
    float edn = ed[node];

    float m = -FLT_MAX;
    for (int j = b0 + lane; j < b1; j += 32) {
        float e = es[csr_src[j]] + edn;
        e = (e > 0.f) ? e : 0.2f * e;
        m = fmaxf(m, e);
    }
    for (int o = 16; o > 0; o >>= 1) m = fmaxf(m, __shfl_down_sync(0xffffffffu, m, o));
    m = __shfl_sync(0xffffffffu, m, 0);

    float s = 0.f;
    for (int j = b0 + lane; j < b1; j += 32) {
        float e = es[csr_src[j]] + edn;
        e = (e > 0.f) ? e : 0.2f * e;
        s += __expf(e - m);
    }
    for (int o = 16; o > 0; o >>= 1) s += __shfl_down_sync(0xffffffffu, s, o);
    s = __shfl_sync(0xffffffffu, s, 0);
    float inv = 1.f / fmaxf(s, 1e-16f);

    const float4* h4 = (const float4*)h;
    float4 acc = make_float4(0.f, 0.f, 0.f, 0.f);
    for (int j = b0; j < b1; j++) {
        int src = csr_src[j];
        float e = es[src] + edn;
        e = (e > 0.f) ? e : 0.2f * e;
        float w = __expf(e - m) * inv;
        float4 hv = h4[src * 32 + lane];
        acc.x += w * hv.x; acc.y += w * hv.y; acc.z += w * hv.z; acc.w += w * hv.w;
    }
    float4 bb = ((const float4*)bias)[lane];
    acc.x = fmaxf(acc.x + bb.x, 0.f); acc.y = fmaxf(acc.y + bb.y, 0.f);
    acc.z = fmaxf(acc.z + bb.z, 0.f); acc.w = fmaxf(acc.w + bb.w, 0.f);
    ((float4*)out)[node * 32 + lane] = acc;

    if (outh) {
        __half2 p0 = __halves2half2(__float2half_rn(acc.x), __float2half_rn(acc.y));
        __half2 p1 = __halves2half2(__float2half_rn(acc.z), __float2half_rn(acc.w));
        ((__half2*)outh)[node * 64 + lane * 2]     = p0;
        ((__half2*)outh)[node * 64 + lane * 2 + 1] = p1;
    }
    if (rn) {
        float q = acc.x * acc.x + acc.y * acc.y + acc.z * acc.z + acc.w * acc.w;
        for (int o = 16; o > 0; o >>= 1) q += __shfl_down_sync(0xffffffffu, q, o);
        if (lane == 0) rn[node] = q;
    }
}

__global__ void agg_both(const float* hrI, const float* br, const int* rpr, const int* srcr,
                         const float* esr, const float* edr, float* outr, __half* outhr,
                         float* rnr, int nr,
                         const float* hcI, const float* bc, const int* rpc, const int* srcc,
                         const float* esc, const float* edc, float* outc, __half* outhc,
                         float* rnc, int nc) {
    int wrp = (blockIdx.x * blockDim.x + threadIdx.x) >> 5;
    int lane = threadIdx.x & 31;
    if (wrp < nr)
        agg_body(hrI, br, rpr, srcr, esr, edr, outr, outhr, rnr, wrp, lane);
    else if (wrp < nr + nc)
        agg_body(hcI, bc, rpc, srcc, esc, edc, outc, outhc, rnc, wrp - nr, lane);
}

/* ---------------- KNN selection helpers ---------------- */
__device__ __forceinline__ bool bet(float v, int id, float v2, int id2) {
    return v < v2 || (v == v2 && id < id2);
}
__device__ __forceinline__ void top3_insert(float v, int id, float tv[3], int ti[3]) {
    if (!bet(v, id, tv[2], ti[2])) return;
    tv[2] = v; ti[2] = id;
    if (bet(tv[2], ti[2], tv[1], ti[1])) {
        float f = tv[1]; tv[1] = tv[2]; tv[2] = f;
        int q = ti[1]; ti[1] = ti[2]; ti[2] = q;
    }
    if (bet(tv[1], ti[1], tv[0], ti[0])) {
        float f = tv[0]; tv[0] = tv[1]; tv[1] = f;
        int q = ti[0]; ti[0] = ti[1]; ti[1] = q;
    }
}
#define T8SW(a, b) \
    if (bet(tv[b], ti[b], tv[a], ti[a])) { \
        float f_ = tv[a]; tv[a] = tv[b]; tv[b] = f_; \
        int q_ = ti[a]; ti[a] = ti[b]; ti[b] = q_; }
__device__ __forceinline__ void top8_insert(float s, int id, float tv[8], int ti[8]) {
    if (!bet(s, id, tv[7], ti[7])) return;
    tv[7] = s; ti[7] = id;
    T8SW(6, 7) T8SW(5, 6) T8SW(4, 5) T8SW(3, 4) T8SW(2, 3) T8SW(1, 2) T8SW(0, 1)
}

/* Persistent wmma KNN: A fragments cached in registers per c-tile. */
__global__ void __launch_bounds__(256, 2)
knn_wmma_kernel(const __half* __restrict__ hch, const __half* __restrict__ hrh,
                const float* __restrict__ rn,
                int n_c, int n_r, int n_rtiles, int tiles_per, int n_items,
                float* __restrict__ pv, int* __restrict__ pi) {
    extern __shared__ char dsm[];
    __half* As  = (__half*)dsm;
    __half* Bs  = As + 128 * LDT;
    float*  scr = (float*)(Bs + 2 * BTILE * LDT);
    __shared__ int s_item;

    int tid = threadIdx.x, wid = tid >> 5, lane = tid & 31;
    int crow = lane & 15, chalf = lane >> 4;
    float* myscr = scr + wid * 256;
    unsigned bbase = smem_u32(Bs);

    int row0 = tid >> 4, k80 = tid & 15;
    int prev_ct = -1;
    wmma::fragment<wmma::matrix_a, 16, 16, 16, __half, wmma::row_major> af[8];

    for (;;) {
        __syncthreads();
        if (tid == 0) s_item = atomicAdd(&g_work, 1);
        __syncthreads();
        int item = s_item;
        if (item >= n_items) break;
        int ct = item / RSPLIT;
        int rs = item - ct * RSPLIT;
        int cbase = ct * 128;
        int t0 = rs * tiles_per;
        int t1 = min(t0 + tiles_per, n_rtiles);
        int my_c = cbase + wid * 16 + crow;

        float tv[8]; int ti[8];
#pragma unroll
        for (int s = 0; s < 8; s++) { tv[s] = FLT_MAX; ti[s] = 0x7fffffff; }

        if (t0 < t1) {
            if (ct != prev_ct) {
#pragma unroll
                for (int m = 0; m < 8; m++) {
                    int idx = tid + m * 256;
                    int row = idx >> 4, k8 = idx & 15;
                    int c = cbase + row;
                    uint4 v = make_uint4(0, 0, 0, 0);
                    if (c < n_c) v = ((const uint4*)hch)[c * 16 + k8];
                    *(uint4*)&As[row * LDT + k8 * 8] = v;
                }
                __syncthreads();
#pragma unroll
                for (int k = 0; k < 8; k++)
                    wmma::load_matrix_sync(af[k], &As[(wid * 16) * LDT + k * 16], LDT);
                prev_ct = ct;
            }

            {
                int rbase = t0 * BTILE;
#pragma unroll
                for (int m = 0; m < 4; m++) {
                    int row = row0 + m * 16;
                    int r = rbase + row;
                    int ok = (r < n_r);
                    const void* src = hrh + (size_t)(ok ? r : 0) * 128 + k80 * 8;
                    cp_async16(bbase + (row * LDT + k80 * 8) * 2, src, ok ? 16 : 0);
                }
                CP_COMMIT();
            }

            for (int tt = t0; tt < t1; tt++) {
                int cur = (tt - t0) & 1;
                CP_WAIT0();
                __syncthreads();
                if (tt + 1 < t1) {
                    int nxt = cur ^ 1;
                    int rbase2 = (tt + 1) * BTILE;
#pragma unroll
                    for (int m = 0; m < 4; m++) {
                        int row = row0 + m * 16;
                        int r = rbase2 + row;
                        int ok = (r < n_r);
                        const void* src = hrh + (size_t)(ok ? r : 0) * 128 + k80 * 8;
                        cp_async16(bbase + (nxt * BTILE * LDT + row * LDT + k80 * 8) * 2, src, ok ? 16 : 0);
                    }
                    CP_COMMIT();
                }

                const __half* Bc = Bs + cur * BTILE * LDT;
                int rbase = tt * BTILE;

                wmma::fragment<wmma::accumulator, 16, 16, 16, float> acc[4];
#pragma unroll
                for (int f = 0; f < 4; f++) wmma::fill_fragment(acc[f], 0.f);
#pragma unroll
                for (int k = 0; k < 8; k++) {
#pragma unroll
                    for (int f = 0; f < 4; f++) {
                        wmma::fragment<wmma::matrix_b, 16, 16, 16, __half, wmma::col_major> bf;
                        wmma::load_matrix_sync(bf, &Bc[(f * 16) * LDT + k * 16], LDT);
                        wmma::mma_sync(acc[f], af[k], bf, acc[f]);
                    }
                }

#pragma unroll
                for (int f = 0; f < 4; f++) {
                    wmma::store_matrix_sync(myscr, acc[f], 16, wmma::mem_row_major);
                    __syncwarp();
                    int cb = f * 16 + chalf * 8;
#pragma unroll
                    for (int j = 0; j < 8; j++) {
                        int r = rbase + cb + j;
                        float rv = (r < n_r) ? rn[r] : 1e30f;
                        float d = myscr[crow * 16 + chalf * 8 + j];
                        top8_insert(fmaf(-2.f, d, rv), r, tv, ti);
                    }
                    __syncwarp();
                }
            }
        }

        if (my_c < n_c) {
            int ebase = (rs * 2 + chalf) * 8;
#pragma unroll
            for (int s = 0; s < 8; s++) {
                pv[(ebase + s) * MAX_NC_PAD + my_c] = tv[s];
                pi[(ebase + s) * MAX_NC_PAD + my_c] = ti[s];
            }
        }
    }
}

/* ---- fused post: merge + exact rescore + top3 + pooling, warp per collider ---- */
__global__ void post_warp_kernel(const float* __restrict__ pv, const int* __restrict__ pi,
                                 const float* __restrict__ hc, const float* __restrict__ hr,
                                 const float* __restrict__ rn,
                                 float* __restrict__ pool, int* __restrict__ cnt,
                                 int n_c, int n_r) {
    int c = (blockIdx.x * blockDim.x + threadIdx.x) >> 5;
    int lane = threadIdx.x & 31;
    if (c >= n_c) return;

    /* 1. lane-local sorted top-8 over its slice of NPART partial entries */
    float tv[8]; int ti[8];
#pragma unroll
    for (int s = 0; s < 8; s++) { tv[s] = FLT_MAX; ti[s] = 0x7fffffff; }
    for (int e = lane; e < NPART; e += 32) {
        int id = pi[e * MAX_NC_PAD + c];
        if ((unsigned)id < (unsigned)n_r)
            top8_insert(pv[e * MAX_NC_PAD + c], id, tv, ti);
    }

    /* 2. warp tournament: pop global top-8 by strict (v,id) order */
    float cv[TOPP]; int ci[TOPP];
    int hp = 0;
#pragma unroll
    for (int round = 0; round < TOPP; round++) {
        float mv = (hp < 8) ? tv[hp] : FLT_MAX;
        int   mi = (hp < 8) ? ti[hp] : 0x7fffffff;
        float bv_ = mv; int bi_ = mi;
        for (int o = 16; o > 0; o >>= 1) {
            float ov = __shfl_down_sync(0xffffffffu, bv_, o);
            int   oi = __shfl_down_sync(0xffffffffu, bi_, o);
            if (bet(ov, oi, bv_, bi_)) { bv_ = ov; bi_ = oi; }
        }
        bv_ = __shfl_sync(0xffffffffu, bv_, 0);
        bi_ = __shfl_sync(0xffffffffu, bi_, 0);
        unsigned ball = __ballot_sync(0xffffffffu,
                                      hp < 8 && tv[hp] == bv_ && ti[hp] == bi_);
        int wlane = __ffs(ball) - 1;
        if (lane == wlane) hp++;
        cv[round] = bv_; ci[round] = bi_;
    }

    /* 3. exact fp32 rescore of 8 candidates (warp dot each) */
    float4 a = ((const float4*)hc)[c * 32 + lane];
    float sc8[TOPP];
#pragma unroll
    for (int j = 0; j < TOPP; j++) {
        int id = ci[j];
        float s = FLT_MAX;
        if ((unsigned)id < (unsigned)n_r) {
            float4 b = ((const float4*)hr)[id * 32 + lane];
            float d = a.x * b.x + a.y * b.y + a.z * b.z + a.w * b.w;
            for (int o = 16; o > 0; o >>= 1) d += __shfl_down_sync(0xffffffffu, d, o);
            d = __shfl_sync(0xffffffffu, d, 0);
            s = rn[id] - 2.f * d;
        }
        sc8[j] = s;
    }

    /* 4. top-3 (all lanes redundantly) */
    float bv3[3] = {FLT_MAX, FLT_MAX, FLT_MAX};
    int   bi3[3] = {0x7fffffff, 0x7fffffff, 0x7fffffff};
#pragma unroll
    for (int j = 0; j < TOPP; j++) {
        if ((unsigned)ci[j] < (unsigned)n_r)
            top3_insert(sc8[j], ci[j], bv3, bi3);
    }

    /* 5. pooling atomics */
#pragma unroll
    for (int s = 0; s < KNN_K; s++) {
        int idx = bi3[s];
        if (lane == 0) atomicAdd(&cnt[idx], 1);
        atomicAdd(&pool[idx * HID + lane * 4 + 0], a.x);
        atomicAdd(&pool[idx * HID + lane * 4 + 1], a.y);
        atomicAdd(&pool[idx * HID + lane * 4 + 2], a.z);
        atomicAdd(&pool[idx * HID + lane * 4 + 3], a.w);
    }
}

__global__ void decode_kernel(const float* __restrict__ hr, const float* __restrict__ pool,
                              const int* __restrict__ cnt, const float* __restrict__ Wd,
                              const float* __restrict__ bd, float* __restrict__ out, int n) {
    int i = (blockIdx.x * blockDim.x + threadIdx.x) >> 5;
    int lane = threadIdx.x & 31;
    if (i >= n) return;
    float inv = 1.f / fmaxf((float)cnt[i], 1.f);
    float a0 = 0.f, a1 = 0.f, a2 = 0.f;
    for (int f = lane; f < HID; f += 32) {
        float v = hr[i * HID + f];
        a0 += v * Wd[f * 3 + 0]; a1 += v * Wd[f * 3 + 1]; a2 += v * Wd[f * 3 + 2];
        float p = pool[i * HID + f] * inv;
        a0 += p * Wd[(HID + f) * 3 + 0]; a1 += p * Wd[(HID + f) * 3 + 1]; a2 += p * Wd[(HID + f) * 3 + 2];
    }
    for (int o = 16; o > 0; o >>= 1) {
        a0 += __shfl_down_sync(0xffffffffu, a0, o);
        a1 += __shfl_down_sync(0xffffffffu, a1, o);
        a2 += __shfl_down_sync(0xffffffffu, a2, o);
    }
    if (lane == 0) {
        out[i * 3 + 0] = a0 + bd[0];
        out[i * 3 + 1] = a1 + bd[1];
        out[i * 3 + 2] = a2 + bd[2];
    }
}

/* ---------------- host ---------------- */
extern "C" void kernel_launch(void* const* d_in, const int* in_sizes, int n_in,
                              void* d_out, int out_size) {
    const float* x_r  = (const float*)d_in[0];
    const float* x_c  = (const float*)d_in[1];
    const int*   ei_r = (const int*)d_in[2];
    const int*   ei_c = (const int*)d_in[3];
    const float* W_r1 = (const float*)d_in[5];
    const float* as_r1 = (const float*)d_in[6];
    const float* ad_r1 = (const float*)d_in[7];
    const float* b_r1  = (const float*)d_in[8];
    const float* W_r2 = (const float*)d_in[9];
    const float* as_r2 = (const float*)d_in[10];
    const float* ad_r2 = (const float*)d_in[11];
    const float* b_r2  = (const float*)d_in[12];
    const float* W_c1 = (const float*)d_in[13];
    const float* as_c1 = (const float*)d_in[14];
    const float* ad_c1 = (const float*)d_in[15];
    const float* b_c1  = (const float*)d_in[16];
    const float* W_c2 = (const float*)d_in[17];
    const float* as_c2 = (const float*)d_in[18];
    const float* ad_c2 = (const float*)d_in[19];
    const float* b_c2  = (const float*)d_in[20];
    const float* W_dec = (const float*)d_in[21];
    const float* b_dec = (const float*)d_in[22];
    float* out = (float*)d_out;

    int n_r = in_sizes[0] / 6;
    int n_c = in_sizes[1] / 6;
    int E_r = in_sizes[2] / 2;
    int E_c = in_sizes[3] / 2;

    float *lin, *linc, *hr1, *hr, *hc1, *hc, *es, *ed, *esc, *edc, *rnorm, *pv, *pool;
    __half *hch, *hrh;
    int *degr, *degc, *rowptr, *rowptrc, *wp, *wpc, *bsum, *bsumc;
    int *csr_src, *csr_srcc, *pi, *cnt, *work;
    cudaGetSymbolAddress((void**)&lin, g_lin);
    cudaGetSymbolAddress((void**)&linc, g_linc);
    cudaGetSymbolAddress((void**)&hr1, g_hr1);
    cudaGetSymbolAddress((void**)&hr,  g_hr);
    cudaGetSymbolAddress((void**)&hc1, g_hc1);
    cudaGetSymbolAddress((void**)&hc,  g_hc);
    cudaGetSymbolAddress((void**)&es,  g_es);
    cudaGetSymbolAddress((void**)&ed,  g_ed);
    cudaGetSymbolAddress((void**)&esc, g_esc);
    cudaGetSymbolAddress((void**)&edc, g_edc);
    cudaGetSymbolAddress((void**)&degr, g_degr);
    cudaGetSymbolAddress((void**)&degc, g_degc);
    cudaGetSymbolAddress((void**)&rowptr, g_rowptr);
    cudaGetSymbolAddress((void**)&rowptrc, g_rowptrc);
    cudaGetSymbolAddress((void**)&wp,  g_wp);
    cudaGetSymbolAddress((void**)&wpc, g_wpc);
    cudaGetSymbolAddress((void**)&bsum, g_bsum);
    cudaGetSymbolAddress((void**)&bsumc, g_bsumc);
    cudaGetSymbolAddress((void**)&csr_src, g_csr_src);
    cudaGetSymbolAddress((void**)&csr_srcc, g_csr_srcc);
    cudaGetSymbolAddress((void**)&rnorm, g_rnorm);
    cudaGetSymbolAddress((void**)&hch, g_hch);
    cudaGetSymbolAddress((void**)&hrh, g_hrh);
    cudaGetSymbolAddress((void**)&pv, g_pv);
    cudaGetSymbolAddress((void**)&pi, g_pi);
    cudaGetSymbolAddress((void**)&pool, g_pool);
    cudaGetSymbolAddress((void**)&cnt, g_cnt);
    cudaGetSymbolAddress((void**)&work, g_work);

    size_t gemm_smem = (size_t)(128 * 128 + 64 * LDX) * sizeof(float);
    cudaFuncSetAttribute(gemm128_both, cudaFuncAttributeMaxDynamicSharedMemorySize,
                         (int)gemm_smem);

    {
        long np = (long)n_r * HID;
        long total = (long)n_r + n_c + np + n_r + 1;
        int zb = (int)((total + 255) / 256);
        if (zb > 4096) zb = 4096;
        zero_kernel<<<zb, 256>>>(degr, n_r, degc, n_c, pool, np, cnt, work);
    }

    int totr = E_r + n_r, totc = E_c + n_c;
    int ncr = (n_r + SCHUNK - 1) / SCHUNK;
    int ncc = (n_c + SCHUNK - 1) / SCHUNK;

    deg_both<<<(totr + totc + 255) / 256, 256>>>(ei_r, E_r, n_r, degr, ei_c, E_c, n_c, degc);
    scan_p1_both<<<ncr + ncc, 256>>>(degr, n_r, ncr, bsum, degc, n_c, bsumc);
    scan_p2_both<<<2, 32>>>(bsum, ncr, n_r, rowptr, bsumc, ncc, n_c, rowptrc);
    scan_p3_both<<<ncr + ncc, 256>>>(degr, n_r, ncr, bsum, rowptr, wp,
                                     degc, n_c, bsumc, rowptrc, wpc);
    scatter_both<<<(totr + totc + 255) / 256, 256>>>(ei_r, E_r, n_r, wp, csr_src,
                                                     ei_c, E_c, n_c, wpc, csr_srcc);

    lin1_both<<<(n_r + n_c + 7) / 8, 256>>>(x_r, W_r1, as_r1, ad_r1, hr1, es, ed, n_r,
                                            x_c, W_c1, as_c1, ad_c1, hc1, esc, edc, n_c);
    agg_both<<<(n_r + n_c + 7) / 8, 256>>>(hr1, b_r1, rowptr, csr_src, es, ed,
                                           lin, (__half*)0, (float*)0, n_r,
                                           hc1, b_c1, rowptrc, csr_srcc, esc, edc,
                                           linc, (__half*)0, (float*)0, n_c);
    {
        int splitB = (int)((long)152 * n_r / (n_r + n_c));
        if (splitB < 1) splitB = 1;
        if (splitB > 151) splitB = 151;
        gemm128_both<<<152, 256, gemm_smem>>>(lin, W_r2, as_r2, ad_r2, hr1, es, ed, n_r, splitB,
                                              linc, W_c2, as_c2, ad_c2, hc1, esc, edc, n_c);
    }
    agg_both<<<(n_r + n_c + 7) / 8, 256>>>(hr1, b_r2, rowptr, csr_src, es, ed,
                                           hr, hrh, rnorm, n_r,
                                           hc1, b_c2, rowptrc, csr_srcc, esc, edc,
                                           hc, hch, (float*)0, n_c);

    /* KNN */
    int n_rtiles = (n_r + BTILE - 1) / BTILE;
    int tiles_per = (n_rtiles + RSPLIT - 1) / RSPLIT;
    int nct = (n_c + 127) / 128;
    int n_items = nct * RSPLIT;
    size_t knn_smem = (size_t)((128 + 2 * BTILE) * LDT) * sizeof(__half)
                    + (size_t)(8 * 256) * sizeof(float);
    cudaFuncSetAttribute(knn_wmma_kernel, cudaFuncAttributeMaxDynamicSharedMemorySize,
                         (int)knn_smem);
    knn_wmma_kernel<<<KNN_BLOCKS, 256, knn_smem>>>(hch, hrh, rnorm, n_c, n_r,
                                                   n_rtiles, tiles_per, n_items, pv, pi);

    /* fused merge + rescore + top3 + pooling */
    post_warp_kernel<<<(n_c * 32 + 255) / 256, 256>>>(pv, pi, hc, hr, rnorm,
                                                      pool, cnt, n_c, n_r);
    decode_kernel<<<(n_r * 32 + 255) / 256, 256>>>(hr, pool, cnt, W_dec, b_dec, out, n_r);
}